// round 11
// baseline (speedup 1.0000x reference)
#include <cuda_runtime.h>
#include <cuda_bf16.h>
#include <math.h>
#include <stdint.h>

// ===================== scratch (static device arrays) ========================
__device__ float g_xf [4096UL * 512];
__device__ float g_Wsf[1536UL * 512];
__device__ float g_Wmf[12288UL * 1536];
__device__ float g_Wrf[512UL * 4096];
__device__ float g_h1f[4096UL * 1536];
__device__ float g_h2f[4096UL * 12288];
__device__ float g_sc [16UL * 2048 * 2048];
__device__ float g_Pf [16UL * 2048 * 2048];
__device__ float g_Vtf[16UL * 512 * 2048];
__device__ float g_apf[4096UL * 4096];

// ===================== helpers (base-target PTX only) ========================
__device__ __forceinline__ uint32_t smem_u32(const void* p) {
    uint32_t a;
    asm("{ .reg .u64 t; cvta.to.shared.u64 t, %1; cvt.u32.u64 %0, t; }"
        : "=r"(a) : "l"(p));
    return a;
}

__device__ __forceinline__ void cp16(uint32_t s, const void* g) {
    asm volatile("cp.async.cg.shared.global [%0], [%1], 16;"
                 :: "r"(s), "l"(g) : "memory");
}

__device__ __forceinline__ void ldsm4(uint32_t* r, uint32_t addr) {
    asm volatile("ldmatrix.sync.aligned.m8n8.x4.shared.b16 {%0,%1,%2,%3}, [%4];"
                 : "=r"(r[0]), "=r"(r[1]), "=r"(r[2]), "=r"(r[3]) : "r"(addr));
}

__device__ __forceinline__ void mma_tf32(float* c, const uint32_t* a, const uint32_t* b) {
    asm volatile(
        "mma.sync.aligned.m16n8k8.row.col.f32.tf32.tf32.f32 "
        "{%0,%1,%2,%3}, {%4,%5,%6,%7}, {%8,%9}, {%0,%1,%2,%3};"
        : "+f"(c[0]), "+f"(c[1]), "+f"(c[2]), "+f"(c[3])
        : "r"(a[0]), "r"(a[1]), "r"(a[2]), "r"(a[3]), "r"(b[0]), "r"(b[1]));
}

__device__ __forceinline__ float round_tf32f(float x) {
    uint32_t v = __float_as_uint(x);
    asm("cvt.rna.tf32.f32 %0, %0;" : "+r"(v));
    return __uint_as_float(v);
}

// fp32 tile swizzle: [rows][32 fp32] rows of 128B, 16B chunks
__device__ __forceinline__ uint32_t swz32(int row, int chunk) {
    return (uint32_t)(row * 128 + ((chunk ^ (row & 7)) << 4));
}

// ===================== tf32 GEMM (128x128x32, 64x64 warp tiles) ==============
// C = A @ B^T. A: M x K (lda), B: N x K (ldb), fp32 already tf32-rounded.
// 128 thr (4 warps, 2M x 2N), warp tile 64x64, 3-stage, 2 CTAs/SM.
#define ATILE32 16384               // 128 x 32 fp32
#define STAGE32 (2 * ATILE32)       // 32768
#define NSTAGE 3
#define SMEM_T32 (NSTAGE * STAGE32) // 98304

__global__ __launch_bounds__(128, 2)
void gemm_tf32(const float* __restrict__ A, const float* __restrict__ B,
               float* __restrict__ C, const float* __restrict__ bias,
               int K, int lda, int ldb, int ldc, int NH,
               size_t sAh_, size_t sAb_, size_t sBh_, size_t sBb_,
               size_t sCh_, size_t sCb_, int round_out)
{
    extern __shared__ char smem[];
    const uint32_t sbase = smem_u32(smem);
    const int tid = threadIdx.x, lane = tid & 31, w = tid >> 5;
    const int wm = w & 1, wn = w >> 1;  // 2M x 2N warps, warp tile 64x64

    const int z = blockIdx.z, hb = z % NH, bb = z / NH;
    const size_t offA = (size_t)hb * sAh_ + (size_t)bb * sAb_;
    const size_t offB = (size_t)hb * sBh_ + (size_t)bb * sBb_;
    const size_t offC = (size_t)hb * sCh_ + (size_t)bb * sCb_;
    const int n0 = blockIdx.x * 128;

    const float* ag = A + offA + (size_t)(blockIdx.y * 128) * lda;
    const float* bg = B + offB + (size_t)n0 * ldb;

    float acc[4][8][4];  // 64x64 per warp: 4 m16-tiles x 8 n8-tiles
#pragma unroll
    for (int mt = 0; mt < 4; mt++)
#pragma unroll
        for (int j = 0; j < 8; j++)
#pragma unroll
            for (int q = 0; q < 4; q++) acc[mt][j][q] = 0.0f;

    const int niter = K >> 5;

    auto issue = [&](int it) {
        const uint32_t sb = sbase + (uint32_t)(it % NSTAGE) * STAGE32;
        const int k0 = it << 5;
        // A and B: 1024 chunks each -> 8/thread each (128 threads)
#pragma unroll
        for (int q = 0; q < 8; q++) {
            const int idx = tid + q * 128;
            const int r = idx >> 3, c = idx & 7;
            const uint32_t so = swz32(r, c);
            cp16(sb + so,           ag + (size_t)r * lda + k0 + c * 4);
            cp16(sb + ATILE32 + so, bg + (size_t)r * ldb + k0 + c * 4);
        }
        asm volatile("cp.async.commit_group;" ::: "memory");
    };

    issue(0);
    if (niter > 1) issue(1);

    const int frow = lane & 15;
    const int fch  = lane >> 4;

    for (int i = 0; i < niter; i++) {
        if (i + 1 < niter)
            asm volatile("cp.async.wait_group 1;" ::: "memory");
        else
            asm volatile("cp.async.wait_group 0;" ::: "memory");
        __syncthreads();
        if (i + 2 < niter) issue(i + 2);

        const uint32_t sb = sbase + (uint32_t)(i % NSTAGE) * STAGE32;
        const uint32_t sbB = sb + ATILE32;
#pragma unroll
        for (int ks = 0; ks < 4; ks++) {
            const int ch = 2 * ks + fch;
            uint32_t af[4][4], bf[8][2];
#pragma unroll
            for (int mt = 0; mt < 4; mt++)
                ldsm4(af[mt], sb + swz32(wm * 64 + mt * 16 + frow, ch));
#pragma unroll
            for (int np = 0; np < 4; np++) {
                uint32_t tmp[4];
                ldsm4(tmp, sbB + swz32(wn * 64 + np * 16 + frow, ch));
                bf[2 * np][0]     = tmp[0];
                bf[2 * np + 1][0] = tmp[1];
                bf[2 * np][1]     = tmp[2];
                bf[2 * np + 1][1] = tmp[3];
            }
#pragma unroll
            for (int mt = 0; mt < 4; mt++)
#pragma unroll
                for (int nt = 0; nt < 8; nt++)
                    mma_tf32(acc[mt][nt], af[mt], bf[nt]);
        }
    }

    // ---------------- epilogue ----------------
    const int gid = lane >> 2, tig = lane & 3;
    const int row0 = blockIdx.y * 128 + wm * 64;
    const int col0 = n0 + wn * 64;
#pragma unroll
    for (int mt = 0; mt < 4; mt++) {
#pragma unroll
        for (int j = 0; j < 8; j++) {
            const int r = row0 + mt * 16 + gid;
            const int c = col0 + j * 8 + tig * 2;
            float b0 = 0.f, b1 = 0.f;
            if (bias) { b0 = __ldg(&bias[c]); b1 = __ldg(&bias[c + 1]); }
            float v0 = acc[mt][j][0] + b0, v1 = acc[mt][j][1] + b1;
            float v2 = acc[mt][j][2] + b0, v3 = acc[mt][j][3] + b1;
            if (round_out) {
                v0 = round_tf32f(v0); v1 = round_tf32f(v1);
                v2 = round_tf32f(v2); v3 = round_tf32f(v3);
            }
            const size_t o0 = offC + (size_t)r * ldc + c;
            const size_t o1 = offC + (size_t)(r + 8) * ldc + c;
            *(float2*)(C + o0) = make_float2(v0, v1);
            *(float2*)(C + o1) = make_float2(v2, v3);
        }
    }
}

// ===================== aux kernels ===========================================
__global__ void round_copy_tf32(const float* __restrict__ in,
                                float* __restrict__ out, size_t n)
{
    size_t i = ((size_t)blockIdx.x * blockDim.x + threadIdx.x) * 4;
    const size_t stride = (size_t)gridDim.x * blockDim.x * 4;
    for (; i < n; i += stride) {
        float4 v = *(const float4*)(in + i);
        v.x = round_tf32f(v.x); v.y = round_tf32f(v.y);
        v.z = round_tf32f(v.z); v.w = round_tf32f(v.w);
        *(float4*)(out + i) = v;
    }
}

__global__ void softmax_tf32(const float* __restrict__ sc,
                             float* __restrict__ pf, float scale)
{
    const int tid = threadIdx.x;
    const size_t base = (size_t)blockIdx.x * 2048;
    const float* p = sc + base;
    __shared__ float red[256];

    float v[8];
    float mx = -1e30f;
#pragma unroll
    for (int i = 0; i < 8; i++) {
        v[i] = p[tid + i * 256] * scale;
        mx = fmaxf(mx, v[i]);
    }
    red[tid] = mx;
    __syncthreads();
#pragma unroll
    for (int s = 128; s > 0; s >>= 1) {
        if (tid < s) red[tid] = fmaxf(red[tid], red[tid + s]);
        __syncthreads();
    }
    mx = red[0];
    __syncthreads();

    float sum = 0.0f;
#pragma unroll
    for (int i = 0; i < 8; i++) {
        v[i] = __expf(v[i] - mx);
        sum += v[i];
    }
    red[tid] = sum;
    __syncthreads();
#pragma unroll
    for (int s = 128; s > 0; s >>= 1) {
        if (tid < s) red[tid] += red[tid + s];
        __syncthreads();
    }
    const float inv = 1.0f / red[0];
#pragma unroll
    for (int i = 0; i < 8; i++)
        pf[base + tid + i * 256] = round_tf32f(v[i] * inv);
}

// V^T per (b,h): Vt[d][sk] = h2f[(b,sk)][h*1536+1024+d]  (already tf32-rounded)
__global__ void transpose_v(const float* __restrict__ h2f,
                            float* __restrict__ vtf)
{
    __shared__ float t[32][33];
    const int z = blockIdx.z, b = z >> 3, h = z & 7;
    const int sk0 = blockIdx.x * 32, d0 = blockIdx.y * 32;
    const int tx = threadIdx.x, ty = threadIdx.y;  // 32 x 8
    const size_t srcbase = (size_t)b * 2048 * 12288 + h * 1536 + 1024;
#pragma unroll
    for (int j = 0; j < 4; j++) {
        int sk = sk0 + ty + j * 8;
        t[ty + j * 8][tx] = h2f[srcbase + (size_t)sk * 12288 + d0 + tx];
    }
    __syncthreads();
    const size_t dstbase = (size_t)(b * 8 + h) * 512 * 2048;
#pragma unroll
    for (int j = 0; j < 4; j++) {
        int d = d0 + ty + j * 8;
        vtf[dstbase + (size_t)d * 2048 + sk0 + tx] = t[tx][ty + j * 8];
    }
}

// =============================================================================
extern "C" void kernel_launch(void* const* d_in, const int* in_sizes, int n_in,
                              void* d_out, int out_size)
{
    const float* x     = (const float*)d_in[0];
    const float* W_sep = (const float*)d_in[1];
    const float* b_sep = (const float*)d_in[2];
    const float* W_mul = (const float*)d_in[3];
    const float* b_mul = (const float*)d_in[4];
    const float* W_res = (const float*)d_in[5];
    const float* b_res = (const float*)d_in[6];
    float* out = (float*)d_out;

    float *xf, *Wsf, *Wmf, *Wrf, *h1f, *h2f, *sc, *Pf, *Vtf, *apf;
    cudaGetSymbolAddress((void**)&xf,  g_xf);
    cudaGetSymbolAddress((void**)&Wsf, g_Wsf);
    cudaGetSymbolAddress((void**)&Wmf, g_Wmf);
    cudaGetSymbolAddress((void**)&Wrf, g_Wrf);
    cudaGetSymbolAddress((void**)&h1f, g_h1f);
    cudaGetSymbolAddress((void**)&h2f, g_h2f);
    cudaGetSymbolAddress((void**)&sc,  g_sc);
    cudaGetSymbolAddress((void**)&Pf,  g_Pf);
    cudaGetSymbolAddress((void**)&Vtf, g_Vtf);
    cudaGetSymbolAddress((void**)&apf, g_apf);

    cudaFuncSetAttribute(gemm_tf32, cudaFuncAttributeMaxDynamicSharedMemorySize, SMEM_T32);

    const size_t S = 2048, D = 512, H = 8;

    // tf32-round inputs & weights
    round_copy_tf32<<<512,  256>>>(x,     xf,  4096UL * 512);
    round_copy_tf32<<<512,  256>>>(W_sep, Wsf, 1536UL * 512);
    round_copy_tf32<<<2048, 256>>>(W_mul, Wmf, 12288UL * 1536);

    // GEMM1: h1 = x @ W_sep^T + b_sep   [4096 x 1536], K=512 (out tf32-rounded)
    gemm_tf32<<<dim3(12, 32, 1), 128, SMEM_T32>>>(
        xf, Wsf, h1f, b_sep,
        512, 512, 512, 1536, 1, 0, 0, 0, 0, 0, 0, 1);

    // GEMM2: h2 = h1 @ W_mul^T + b_mul  [4096 x 12288], K=1536 (out tf32-rounded)
    gemm_tf32<<<dim3(96, 32, 1), 128, SMEM_T32>>>(
        h1f, Wmf, h2f, b_mul,
        1536, 1536, 1536, 12288, 1, 0, 0, 0, 0, 0, 0, 1);

    // QK^T batched (z = b*8 + h): sc = Q @ K^T  [2048 x 2048], K=512
    gemm_tf32<<<dim3(16, 16, 16), 128, SMEM_T32>>>(
        h2f, h2f + 512, sc, nullptr,
        512, 12288, 12288, 2048, 8,
        1536, S * 12288, 1536, S * 12288,
        S * S, H * S * S, 0);

    // softmax(scale * sc) -> P (tf32-rounded fp32)
    softmax_tf32<<<16 * 2048, 256>>>(sc, Pf, 1.0f / sqrtf(512.0f));

    // V^T (values already tf32-rounded in h2f)
    transpose_v<<<dim3(64, 16, 16), dim3(32, 8)>>>(h2f, Vtf);

    round_copy_tf32<<<512, 256>>>(W_res, Wrf, 512UL * 4096);

    // PV batched: ap[b, sq, h*512+d] = P @ Vt^T  [2048 x 512], K=2048 (rounded)
    gemm_tf32<<<dim3(4, 16, 16), 128, SMEM_T32>>>(
        Pf, Vtf, apf, nullptr,
        2048, 2048, 2048, 4096, 8,
        S * S, H * S * S, D * S, H * D * S,
        512, S * 4096, 1);

    // GEMM3: out = ap @ W_res^T + b_res  [4096 x 512], K=4096
    gemm_tf32<<<dim3(4, 32, 1), 128, SMEM_T32>>>(
        apf, Wrf, out, b_res,
        4096, 4096, 4096, 512, 1, 0, 0, 0, 0, 0, 0, 0);
}

// round 12
// speedup vs baseline: 1.0100x; 1.0100x over previous
#include <cuda_runtime.h>
#include <cuda_bf16.h>
#include <math.h>
#include <stdint.h>

// ===================== scratch (static device arrays) ========================
__device__ float g_xf [4096UL * 512];
__device__ float g_Wsf[1536UL * 512];
__device__ float g_Wmf[12288UL * 1536];
__device__ float g_Wrf[512UL * 4096];
__device__ float g_h1f[4096UL * 1536];
__device__ float g_h2f[4096UL * 12288];
__device__ float g_sc [16UL * 2048 * 2048];   // scores; later reused as split-K slabs
__device__ float g_Pf [16UL * 2048 * 2048];
__device__ float g_Vtf[16UL * 512 * 2048];
__device__ float g_apf[4096UL * 4096];

// ===================== helpers (base-target PTX only) ========================
__device__ __forceinline__ uint32_t smem_u32(const void* p) {
    uint32_t a;
    asm("{ .reg .u64 t; cvta.to.shared.u64 t, %1; cvt.u32.u64 %0, t; }"
        : "=r"(a) : "l"(p));
    return a;
}

__device__ __forceinline__ void cp16(uint32_t s, const void* g) {
    asm volatile("cp.async.cg.shared.global [%0], [%1], 16;"
                 :: "r"(s), "l"(g) : "memory");
}

__device__ __forceinline__ void ldsm4(uint32_t* r, uint32_t addr) {
    asm volatile("ldmatrix.sync.aligned.m8n8.x4.shared.b16 {%0,%1,%2,%3}, [%4];"
                 : "=r"(r[0]), "=r"(r[1]), "=r"(r[2]), "=r"(r[3]) : "r"(addr));
}

__device__ __forceinline__ void mma_tf32(float* c, const uint32_t* a, const uint32_t* b) {
    asm volatile(
        "mma.sync.aligned.m16n8k8.row.col.f32.tf32.tf32.f32 "
        "{%0,%1,%2,%3}, {%4,%5,%6,%7}, {%8,%9}, {%0,%1,%2,%3};"
        : "+f"(c[0]), "+f"(c[1]), "+f"(c[2]), "+f"(c[3])
        : "r"(a[0]), "r"(a[1]), "r"(a[2]), "r"(a[3]), "r"(b[0]), "r"(b[1]));
}

__device__ __forceinline__ float round_tf32f(float x) {
    uint32_t v = __float_as_uint(x);
    asm("cvt.rna.tf32.f32 %0, %0;" : "+r"(v));
    return __uint_as_float(v);
}

// fp32 tile swizzle: [rows][32 fp32] rows of 128B, 16B chunks
__device__ __forceinline__ uint32_t swz32(int row, int chunk) {
    return (uint32_t)(row * 128 + ((chunk ^ (row & 7)) << 4));
}

// ===================== tf32 GEMM (128x128x32, 64x64 warp tiles) ==============
// C = A @ B^T. A: M x K (lda), B: N x K (ldb), fp32 already tf32-rounded.
// 128 thr (4 warps, 2M x 2N), warp tile 64x64, 3-stage, 2 CTAs/SM.
#define ATILE32 16384               // 128 x 32 fp32
#define STAGE32 (2 * ATILE32)       // 32768
#define NSTAGE 3
#define SMEM_T32 (NSTAGE * STAGE32) // 98304

__global__ __launch_bounds__(128, 2)
void gemm_tf32(const float* __restrict__ A, const float* __restrict__ B,
               float* __restrict__ C, const float* __restrict__ bias,
               int K, int lda, int ldb, int ldc, int NH,
               size_t sAh_, size_t sAb_, size_t sBh_, size_t sBb_,
               size_t sCh_, size_t sCb_, int round_out)
{
    extern __shared__ char smem[];
    const uint32_t sbase = smem_u32(smem);
    const int tid = threadIdx.x, lane = tid & 31, w = tid >> 5;
    const int wm = w & 1, wn = w >> 1;  // 2M x 2N warps, warp tile 64x64

    const int z = blockIdx.z, hb = z % NH, bb = z / NH;
    const size_t offA = (size_t)hb * sAh_ + (size_t)bb * sAb_;
    const size_t offB = (size_t)hb * sBh_ + (size_t)bb * sBb_;
    const size_t offC = (size_t)hb * sCh_ + (size_t)bb * sCb_;
    const int n0 = blockIdx.x * 128;

    const float* ag = A + offA + (size_t)(blockIdx.y * 128) * lda;
    const float* bg = B + offB + (size_t)n0 * ldb;

    float acc[4][8][4];  // 64x64 per warp: 4 m16-tiles x 8 n8-tiles
#pragma unroll
    for (int mt = 0; mt < 4; mt++)
#pragma unroll
        for (int j = 0; j < 8; j++)
#pragma unroll
            for (int q = 0; q < 4; q++) acc[mt][j][q] = 0.0f;

    const int niter = K >> 5;

    auto issue = [&](int it) {
        const uint32_t sb = sbase + (uint32_t)(it % NSTAGE) * STAGE32;
        const int k0 = it << 5;
#pragma unroll
        for (int q = 0; q < 8; q++) {
            const int idx = tid + q * 128;
            const int r = idx >> 3, c = idx & 7;
            const uint32_t so = swz32(r, c);
            cp16(sb + so,           ag + (size_t)r * lda + k0 + c * 4);
            cp16(sb + ATILE32 + so, bg + (size_t)r * ldb + k0 + c * 4);
        }
        asm volatile("cp.async.commit_group;" ::: "memory");
    };

    issue(0);
    if (niter > 1) issue(1);

    const int frow = lane & 15;
    const int fch  = lane >> 4;

    for (int i = 0; i < niter; i++) {
        if (i + 1 < niter)
            asm volatile("cp.async.wait_group 1;" ::: "memory");
        else
            asm volatile("cp.async.wait_group 0;" ::: "memory");
        __syncthreads();
        if (i + 2 < niter) issue(i + 2);

        const uint32_t sb = sbase + (uint32_t)(i % NSTAGE) * STAGE32;
        const uint32_t sbB = sb + ATILE32;
#pragma unroll
        for (int ks = 0; ks < 4; ks++) {
            const int ch = 2 * ks + fch;
            uint32_t af[4][4], bf[8][2];
#pragma unroll
            for (int mt = 0; mt < 4; mt++)
                ldsm4(af[mt], sb + swz32(wm * 64 + mt * 16 + frow, ch));
#pragma unroll
            for (int np = 0; np < 4; np++) {
                uint32_t tmp[4];
                ldsm4(tmp, sbB + swz32(wn * 64 + np * 16 + frow, ch));
                bf[2 * np][0]     = tmp[0];
                bf[2 * np + 1][0] = tmp[1];
                bf[2 * np][1]     = tmp[2];
                bf[2 * np + 1][1] = tmp[3];
            }
#pragma unroll
            for (int mt = 0; mt < 4; mt++)
#pragma unroll
                for (int nt = 0; nt < 8; nt++)
                    mma_tf32(acc[mt][nt], af[mt], bf[nt]);
        }
    }

    // ---------------- epilogue ----------------
    const int gid = lane >> 2, tig = lane & 3;
    const int row0 = blockIdx.y * 128 + wm * 64;
    const int col0 = n0 + wn * 64;
#pragma unroll
    for (int mt = 0; mt < 4; mt++) {
#pragma unroll
        for (int j = 0; j < 8; j++) {
            const int r = row0 + mt * 16 + gid;
            const int c = col0 + j * 8 + tig * 2;
            float b0 = 0.f, b1 = 0.f;
            if (bias) { b0 = __ldg(&bias[c]); b1 = __ldg(&bias[c + 1]); }
            float v0 = acc[mt][j][0] + b0, v1 = acc[mt][j][1] + b1;
            float v2 = acc[mt][j][2] + b0, v3 = acc[mt][j][3] + b1;
            if (round_out) {
                v0 = round_tf32f(v0); v1 = round_tf32f(v1);
                v2 = round_tf32f(v2); v3 = round_tf32f(v3);
            }
            const size_t o0 = offC + (size_t)r * ldc + c;
            const size_t o1 = offC + (size_t)(r + 8) * ldc + c;
            *(float2*)(C + o0) = make_float2(v0, v1);
            *(float2*)(C + o1) = make_float2(v2, v3);
        }
    }
}

// ===================== aux kernels ===========================================
__global__ void round_copy_tf32(const float* __restrict__ in,
                                float* __restrict__ out, size_t n)
{
    size_t i = ((size_t)blockIdx.x * blockDim.x + threadIdx.x) * 4;
    const size_t stride = (size_t)gridDim.x * blockDim.x * 4;
    for (; i < n; i += stride) {
        float4 v = *(const float4*)(in + i);
        v.x = round_tf32f(v.x); v.y = round_tf32f(v.y);
        v.z = round_tf32f(v.z); v.w = round_tf32f(v.w);
        *(float4*)(out + i) = v;
    }
}

// fused: round two arrays in one launch (blockIdx.y selects pair)
__global__ void round_copy_tf32_2(const float* __restrict__ in0, float* __restrict__ out0, size_t n0,
                                  const float* __restrict__ in1, float* __restrict__ out1, size_t n1)
{
    const float* in  = blockIdx.y ? in1  : in0;
    float*       out = blockIdx.y ? out1 : out0;
    const size_t n   = blockIdx.y ? n1   : n0;
    size_t i = ((size_t)blockIdx.x * blockDim.x + threadIdx.x) * 4;
    const size_t stride = (size_t)gridDim.x * blockDim.x * 4;
    for (; i < n; i += stride) {
        float4 v = *(const float4*)(in + i);
        v.x = round_tf32f(v.x); v.y = round_tf32f(v.y);
        v.z = round_tf32f(v.z); v.w = round_tf32f(v.w);
        *(float4*)(out + i) = v;
    }
}

// out = s0 + s1 + bias[col]  (fp32, 512 cols)
__global__ void add_splitk_bias(const float* __restrict__ s0, const float* __restrict__ s1,
                                const float* __restrict__ bias, float* __restrict__ out,
                                size_t n)
{
    size_t i = ((size_t)blockIdx.x * blockDim.x + threadIdx.x) * 4;
    const size_t stride = (size_t)gridDim.x * blockDim.x * 4;
    for (; i < n; i += stride) {
        float4 a = *(const float4*)(s0 + i);
        float4 b = *(const float4*)(s1 + i);
        const int c = (int)(i & 511);
        a.x += b.x + __ldg(&bias[c]);
        a.y += b.y + __ldg(&bias[c + 1]);
        a.z += b.z + __ldg(&bias[c + 2]);
        a.w += b.w + __ldg(&bias[c + 3]);
        *(float4*)(out + i) = a;
    }
}

__global__ void softmax_tf32(const float* __restrict__ sc,
                             float* __restrict__ pf, float scale)
{
    const int tid = threadIdx.x;
    const size_t base = (size_t)blockIdx.x * 2048;
    const float* p = sc + base;
    __shared__ float red[256];

    float v[8];
    float mx = -1e30f;
#pragma unroll
    for (int i = 0; i < 8; i++) {
        v[i] = p[tid + i * 256] * scale;
        mx = fmaxf(mx, v[i]);
    }
    red[tid] = mx;
    __syncthreads();
#pragma unroll
    for (int s = 128; s > 0; s >>= 1) {
        if (tid < s) red[tid] = fmaxf(red[tid], red[tid + s]);
        __syncthreads();
    }
    mx = red[0];
    __syncthreads();

    float sum = 0.0f;
#pragma unroll
    for (int i = 0; i < 8; i++) {
        v[i] = __expf(v[i] - mx);
        sum += v[i];
    }
    red[tid] = sum;
    __syncthreads();
#pragma unroll
    for (int s = 128; s > 0; s >>= 1) {
        if (tid < s) red[tid] += red[tid + s];
        __syncthreads();
    }
    const float inv = 1.0f / red[0];
#pragma unroll
    for (int i = 0; i < 8; i++)
        pf[base + tid + i * 256] = round_tf32f(v[i] * inv);
}

// V^T per (b,h): Vt[d][sk] = h2f[(b,sk)][h*1536+1024+d]  (already tf32-rounded)
__global__ void transpose_v(const float* __restrict__ h2f,
                            float* __restrict__ vtf)
{
    __shared__ float t[32][33];
    const int z = blockIdx.z, b = z >> 3, h = z & 7;
    const int sk0 = blockIdx.x * 32, d0 = blockIdx.y * 32;
    const int tx = threadIdx.x, ty = threadIdx.y;  // 32 x 8
    const size_t srcbase = (size_t)b * 2048 * 12288 + h * 1536 + 1024;
#pragma unroll
    for (int j = 0; j < 4; j++) {
        int sk = sk0 + ty + j * 8;
        t[ty + j * 8][tx] = h2f[srcbase + (size_t)sk * 12288 + d0 + tx];
    }
    __syncthreads();
    const size_t dstbase = (size_t)(b * 8 + h) * 512 * 2048;
#pragma unroll
    for (int j = 0; j < 4; j++) {
        int d = d0 + ty + j * 8;
        vtf[dstbase + (size_t)d * 2048 + sk0 + tx] = t[tx][ty + j * 8];
    }
}

// =============================================================================
extern "C" void kernel_launch(void* const* d_in, const int* in_sizes, int n_in,
                              void* d_out, int out_size)
{
    const float* x     = (const float*)d_in[0];
    const float* W_sep = (const float*)d_in[1];
    const float* b_sep = (const float*)d_in[2];
    const float* W_mul = (const float*)d_in[3];
    const float* b_mul = (const float*)d_in[4];
    const float* W_res = (const float*)d_in[5];
    const float* b_res = (const float*)d_in[6];
    float* out = (float*)d_out;

    float *xf, *Wsf, *Wmf, *Wrf, *h1f, *h2f, *sc, *Pf, *Vtf, *apf;
    cudaGetSymbolAddress((void**)&xf,  g_xf);
    cudaGetSymbolAddress((void**)&Wsf, g_Wsf);
    cudaGetSymbolAddress((void**)&Wmf, g_Wmf);
    cudaGetSymbolAddress((void**)&Wrf, g_Wrf);
    cudaGetSymbolAddress((void**)&h1f, g_h1f);
    cudaGetSymbolAddress((void**)&h2f, g_h2f);
    cudaGetSymbolAddress((void**)&sc,  g_sc);
    cudaGetSymbolAddress((void**)&Pf,  g_Pf);
    cudaGetSymbolAddress((void**)&Vtf, g_Vtf);
    cudaGetSymbolAddress((void**)&apf, g_apf);

    cudaFuncSetAttribute(gemm_tf32, cudaFuncAttributeMaxDynamicSharedMemorySize, SMEM_T32);

    const size_t S = 2048, D = 512, H = 8;

    // (1) fused rounding of x + W_sep
    round_copy_tf32_2<<<dim3(512, 2), 256>>>(x, xf, 4096UL * 512,
                                             W_sep, Wsf, 1536UL * 512);
    // (2) round W_mul
    round_copy_tf32<<<2048, 256>>>(W_mul, Wmf, 12288UL * 1536);

    // (3) GEMM1: h1 = x @ W_sep^T + b_sep   [4096 x 1536], K=512
    gemm_tf32<<<dim3(12, 32, 1), 128, SMEM_T32>>>(
        xf, Wsf, h1f, b_sep,
        512, 512, 512, 1536, 1, 0, 0, 0, 0, 0, 0, 1);

    // (4) GEMM2 (PROFILED): h2 = h1 @ W_mul^T + b_mul  [4096 x 12288], K=1536
    gemm_tf32<<<dim3(96, 32, 1), 128, SMEM_T32>>>(
        h1f, Wmf, h2f, b_mul,
        1536, 1536, 1536, 12288, 1, 0, 0, 0, 0, 0, 0, 1);

    // (5) QK^T batched: sc = Q @ K^T  [2048 x 2048], K=512
    gemm_tf32<<<dim3(16, 16, 16), 128, SMEM_T32>>>(
        h2f, h2f + 512, sc, nullptr,
        512, 12288, 12288, 2048, 8,
        1536, S * 12288, 1536, S * 12288,
        S * S, H * S * S, 0);

    // (6) softmax(scale * sc) -> P
    softmax_tf32<<<16 * 2048, 256>>>(sc, Pf, 1.0f / sqrtf(512.0f));

    // (7) V^T
    transpose_v<<<dim3(64, 16, 16), dim3(32, 8)>>>(h2f, Vtf);

    // (8) round W_res
    round_copy_tf32<<<512, 256>>>(W_res, Wrf, 512UL * 4096);

    // (9) PV batched: ap = P @ Vt^T  [2048 x 512], K=2048 (rounded out)
    gemm_tf32<<<dim3(4, 16, 16), 128, SMEM_T32>>>(
        Pf, Vtf, apf, nullptr,
        2048, 2048, 2048, 4096, 8,
        S * S, H * S * S, D * S, H * D * S,
        512, S * 4096, 1);

    // (10) GEMM3 split-K=2: partials into sc slabs. z selects K-half via hb.
    //      slab z: sc + z * (4096*512)
    gemm_tf32<<<dim3(4, 32, 2), 128, SMEM_T32>>>(
        apf, Wrf, sc, nullptr,
        2048, 4096, 4096, 512, 2,
        2048, 0, 2048, 0,
        4096UL * 512, 0, 0);

    // (11) out = slab0 + slab1 + b_res
    add_splitk_bias<<<1024, 256>>>(sc, sc + 4096UL * 512, b_res, out, 4096UL * 512);
}

// round 13
// speedup vs baseline: 1.1474x; 1.1360x over previous
#include <cuda_runtime.h>
#include <cuda_bf16.h>
#include <math.h>
#include <stdint.h>

// ===================== scratch (static device arrays) ========================
__device__ float g_xf [4096UL * 512];
__device__ float g_Wst[512UL * 1536];         // W_sep^T, tf32-rounded
__device__ float g_Wmf[12288UL * 1536];       // W_mul, tf32-rounded
__device__ float g_Wcf[12288UL * 512];        // Wc = W_mul @ W_sep, tf32-rounded
__device__ float g_beff[12288];               // b_mul + W_mul @ b_sep (fp32)
__device__ float g_Wrf[512UL * 4096];
__device__ float g_h2f[4096UL * 12288];
__device__ float g_sc [16UL * 2048 * 2048];   // scores; later reused as split-K slabs
__device__ float g_Pf [16UL * 2048 * 2048];
__device__ float g_Vtf[16UL * 512 * 2048];
__device__ float g_apf[4096UL * 4096];

// ===================== helpers (base-target PTX only) ========================
__device__ __forceinline__ uint32_t smem_u32(const void* p) {
    uint32_t a;
    asm("{ .reg .u64 t; cvta.to.shared.u64 t, %1; cvt.u32.u64 %0, t; }"
        : "=r"(a) : "l"(p));
    return a;
}

__device__ __forceinline__ void cp16(uint32_t s, const void* g) {
    asm volatile("cp.async.cg.shared.global [%0], [%1], 16;"
                 :: "r"(s), "l"(g) : "memory");
}

__device__ __forceinline__ void ldsm4(uint32_t* r, uint32_t addr) {
    asm volatile("ldmatrix.sync.aligned.m8n8.x4.shared.b16 {%0,%1,%2,%3}, [%4];"
                 : "=r"(r[0]), "=r"(r[1]), "=r"(r[2]), "=r"(r[3]) : "r"(addr));
}

__device__ __forceinline__ void mma_tf32(float* c, const uint32_t* a, const uint32_t* b) {
    asm volatile(
        "mma.sync.aligned.m16n8k8.row.col.f32.tf32.tf32.f32 "
        "{%0,%1,%2,%3}, {%4,%5,%6,%7}, {%8,%9}, {%0,%1,%2,%3};"
        : "+f"(c[0]), "+f"(c[1]), "+f"(c[2]), "+f"(c[3])
        : "r"(a[0]), "r"(a[1]), "r"(a[2]), "r"(a[3]), "r"(b[0]), "r"(b[1]));
}

__device__ __forceinline__ float round_tf32f(float x) {
    uint32_t v = __float_as_uint(x);
    asm("cvt.rna.tf32.f32 %0, %0;" : "+r"(v));
    return __uint_as_float(v);
}

// fp32 tile swizzle: [rows][32 fp32] rows of 128B, 16B chunks
__device__ __forceinline__ uint32_t swz32(int row, int chunk) {
    return (uint32_t)(row * 128 + ((chunk ^ (row & 7)) << 4));
}

// ===================== tf32 GEMM (128x128x32, 64x64 warp tiles) ==============
// C = A @ B^T. A: M x K (lda), B: N x K (ldb), fp32 already tf32-rounded.
// 128 thr (4 warps, 2M x 2N), warp tile 64x64, 3-stage, 2 CTAs/SM.
#define ATILE32 16384               // 128 x 32 fp32
#define STAGE32 (2 * ATILE32)       // 32768
#define NSTAGE 3
#define SMEM_T32 (NSTAGE * STAGE32) // 98304

__global__ __launch_bounds__(128, 2)
void gemm_tf32(const float* __restrict__ A, const float* __restrict__ B,
               float* __restrict__ C, const float* __restrict__ bias,
               int K, int lda, int ldb, int ldc, int NH,
               size_t sAh_, size_t sAb_, size_t sBh_, size_t sBb_,
               size_t sCh_, size_t sCb_, int round_out)
{
    extern __shared__ char smem[];
    const uint32_t sbase = smem_u32(smem);
    const int tid = threadIdx.x, lane = tid & 31, w = tid >> 5;
    const int wm = w & 1, wn = w >> 1;  // 2M x 2N warps, warp tile 64x64

    const int z = blockIdx.z, hb = z % NH, bb = z / NH;
    const size_t offA = (size_t)hb * sAh_ + (size_t)bb * sAb_;
    const size_t offB = (size_t)hb * sBh_ + (size_t)bb * sBb_;
    const size_t offC = (size_t)hb * sCh_ + (size_t)bb * sCb_;
    const int n0 = blockIdx.x * 128;

    const float* ag = A + offA + (size_t)(blockIdx.y * 128) * lda;
    const float* bg = B + offB + (size_t)n0 * ldb;

    float acc[4][8][4];  // 64x64 per warp: 4 m16-tiles x 8 n8-tiles
#pragma unroll
    for (int mt = 0; mt < 4; mt++)
#pragma unroll
        for (int j = 0; j < 8; j++)
#pragma unroll
            for (int q = 0; q < 4; q++) acc[mt][j][q] = 0.0f;

    const int niter = K >> 5;

    auto issue = [&](int it) {
        const uint32_t sb = sbase + (uint32_t)(it % NSTAGE) * STAGE32;
        const int k0 = it << 5;
#pragma unroll
        for (int q = 0; q < 8; q++) {
            const int idx = tid + q * 128;
            const int r = idx >> 3, c = idx & 7;
            const uint32_t so = swz32(r, c);
            cp16(sb + so,           ag + (size_t)r * lda + k0 + c * 4);
            cp16(sb + ATILE32 + so, bg + (size_t)r * ldb + k0 + c * 4);
        }
        asm volatile("cp.async.commit_group;" ::: "memory");
    };

    issue(0);
    if (niter > 1) issue(1);

    const int frow = lane & 15;
    const int fch  = lane >> 4;

    for (int i = 0; i < niter; i++) {
        if (i + 1 < niter)
            asm volatile("cp.async.wait_group 1;" ::: "memory");
        else
            asm volatile("cp.async.wait_group 0;" ::: "memory");
        __syncthreads();
        if (i + 2 < niter) issue(i + 2);

        const uint32_t sb = sbase + (uint32_t)(i % NSTAGE) * STAGE32;
        const uint32_t sbB = sb + ATILE32;
#pragma unroll
        for (int ks = 0; ks < 4; ks++) {
            const int ch = 2 * ks + fch;
            uint32_t af[4][4], bf[8][2];
#pragma unroll
            for (int mt = 0; mt < 4; mt++)
                ldsm4(af[mt], sb + swz32(wm * 64 + mt * 16 + frow, ch));
#pragma unroll
            for (int np = 0; np < 4; np++) {
                uint32_t tmp[4];
                ldsm4(tmp, sbB + swz32(wn * 64 + np * 16 + frow, ch));
                bf[2 * np][0]     = tmp[0];
                bf[2 * np + 1][0] = tmp[1];
                bf[2 * np][1]     = tmp[2];
                bf[2 * np + 1][1] = tmp[3];
            }
#pragma unroll
            for (int mt = 0; mt < 4; mt++)
#pragma unroll
                for (int nt = 0; nt < 8; nt++)
                    mma_tf32(acc[mt][nt], af[mt], bf[nt]);
        }
    }

    // ---------------- epilogue ----------------
    const int gid = lane >> 2, tig = lane & 3;
    const int row0 = blockIdx.y * 128 + wm * 64;
    const int col0 = n0 + wn * 64;
#pragma unroll
    for (int mt = 0; mt < 4; mt++) {
#pragma unroll
        for (int j = 0; j < 8; j++) {
            const int r = row0 + mt * 16 + gid;
            const int c = col0 + j * 8 + tig * 2;
            float b0 = 0.f, b1 = 0.f;
            if (bias) { b0 = __ldg(&bias[c]); b1 = __ldg(&bias[c + 1]); }
            float v0 = acc[mt][j][0] + b0, v1 = acc[mt][j][1] + b1;
            float v2 = acc[mt][j][2] + b0, v3 = acc[mt][j][3] + b1;
            if (round_out) {
                v0 = round_tf32f(v0); v1 = round_tf32f(v1);
                v2 = round_tf32f(v2); v3 = round_tf32f(v3);
            }
            const size_t o0 = offC + (size_t)r * ldc + c;
            const size_t o1 = offC + (size_t)(r + 8) * ldc + c;
            *(float2*)(C + o0) = make_float2(v0, v1);
            *(float2*)(C + o1) = make_float2(v2, v3);
        }
    }
}

// ===================== aux kernels ===========================================
__global__ void round_copy_tf32(const float* __restrict__ in,
                                float* __restrict__ out, size_t n)
{
    size_t i = ((size_t)blockIdx.x * blockDim.x + threadIdx.x) * 4;
    const size_t stride = (size_t)gridDim.x * blockDim.x * 4;
    for (; i < n; i += stride) {
        float4 v = *(const float4*)(in + i);
        v.x = round_tf32f(v.x); v.y = round_tf32f(v.y);
        v.z = round_tf32f(v.z); v.w = round_tf32f(v.w);
        *(float4*)(out + i) = v;
    }
}

// fused: round two arrays in one launch (blockIdx.y selects pair)
__global__ void round_copy_tf32_2(const float* __restrict__ in0, float* __restrict__ out0, size_t n0,
                                  const float* __restrict__ in1, float* __restrict__ out1, size_t n1)
{
    const float* in  = blockIdx.y ? in1  : in0;
    float*       out = blockIdx.y ? out1 : out0;
    const size_t n   = blockIdx.y ? n1   : n0;
    size_t i = ((size_t)blockIdx.x * blockDim.x + threadIdx.x) * 4;
    const size_t stride = (size_t)gridDim.x * blockDim.x * 4;
    for (; i < n; i += stride) {
        float4 v = *(const float4*)(in + i);
        v.x = round_tf32f(v.x); v.y = round_tf32f(v.y);
        v.z = round_tf32f(v.z); v.w = round_tf32f(v.w);
        *(float4*)(out + i) = v;
    }
}

// prep: blocks [0,768): transpose+round W_sep [1536,512] -> Wst [512,1536]
//       blocks [768,816): b_eff = b_mul + W_mul @ b_sep (fp32)
__global__ void prep_sep(const float* __restrict__ Wsep, float* __restrict__ Wst,
                         const float* __restrict__ Wmul, const float* __restrict__ bsep,
                         const float* __restrict__ bmul, float* __restrict__ beff)
{
    const int tx = threadIdx.x, ty = threadIdx.y;  // 32 x 8
    if (blockIdx.x < 768) {
        __shared__ float t[32][33];
        const int e0 = (blockIdx.x % 48) * 32;
        const int d0 = (blockIdx.x / 48) * 32;
#pragma unroll
        for (int j = 0; j < 4; j++)
            t[ty + j * 8][tx] = Wsep[(size_t)(e0 + ty + j * 8) * 512 + d0 + tx];
        __syncthreads();
#pragma unroll
        for (int j = 0; j < 4; j++)
            Wst[(size_t)(d0 + ty + j * 8) * 1536 + e0 + tx] =
                round_tf32f(t[tx][ty + j * 8]);
    } else {
        const int f = (blockIdx.x - 768) * 256 + ty * 32 + tx;  // 48*256 = 12288
        const float* row = Wmul + (size_t)f * 1536;
        float s = bmul[f];
        for (int e = 0; e < 1536; e++)
            s = fmaf(row[e], __ldg(&bsep[e]), s);
        beff[f] = s;
    }
}

// out = s0 + s1 + bias[col]  (fp32, 512 cols)
__global__ void add_splitk_bias(const float* __restrict__ s0, const float* __restrict__ s1,
                                const float* __restrict__ bias, float* __restrict__ out,
                                size_t n)
{
    size_t i = ((size_t)blockIdx.x * blockDim.x + threadIdx.x) * 4;
    const size_t stride = (size_t)gridDim.x * blockDim.x * 4;
    for (; i < n; i += stride) {
        float4 a = *(const float4*)(s0 + i);
        float4 b = *(const float4*)(s1 + i);
        const int c = (int)(i & 511);
        a.x += b.x + __ldg(&bias[c]);
        a.y += b.y + __ldg(&bias[c + 1]);
        a.z += b.z + __ldg(&bias[c + 2]);
        a.w += b.w + __ldg(&bias[c + 3]);
        *(float4*)(out + i) = a;
    }
}

__global__ void softmax_tf32(const float* __restrict__ sc,
                             float* __restrict__ pf, float scale)
{
    const int tid = threadIdx.x;
    const size_t base = (size_t)blockIdx.x * 2048;
    const float* p = sc + base;
    __shared__ float red[256];

    float v[8];
    float mx = -1e30f;
#pragma unroll
    for (int i = 0; i < 8; i++) {
        v[i] = p[tid + i * 256] * scale;
        mx = fmaxf(mx, v[i]);
    }
    red[tid] = mx;
    __syncthreads();
#pragma unroll
    for (int s = 128; s > 0; s >>= 1) {
        if (tid < s) red[tid] = fmaxf(red[tid], red[tid + s]);
        __syncthreads();
    }
    mx = red[0];
    __syncthreads();

    float sum = 0.0f;
#pragma unroll
    for (int i = 0; i < 8; i++) {
        v[i] = __expf(v[i] - mx);
        sum += v[i];
    }
    red[tid] = sum;
    __syncthreads();
#pragma unroll
    for (int s = 128; s > 0; s >>= 1) {
        if (tid < s) red[tid] += red[tid + s];
        __syncthreads();
    }
    const float inv = 1.0f / red[0];
#pragma unroll
    for (int i = 0; i < 8; i++)
        pf[base + tid + i * 256] = round_tf32f(v[i] * inv);
}

// V^T per (b,h): Vt[d][sk] = h2f[(b,sk)][h*1536+1024+d]  (already tf32-rounded)
__global__ void transpose_v(const float* __restrict__ h2f,
                            float* __restrict__ vtf)
{
    __shared__ float t[32][33];
    const int z = blockIdx.z, b = z >> 3, h = z & 7;
    const int sk0 = blockIdx.x * 32, d0 = blockIdx.y * 32;
    const int tx = threadIdx.x, ty = threadIdx.y;  // 32 x 8
    const size_t srcbase = (size_t)b * 2048 * 12288 + h * 1536 + 1024;
#pragma unroll
    for (int j = 0; j < 4; j++) {
        int sk = sk0 + ty + j * 8;
        t[ty + j * 8][tx] = h2f[srcbase + (size_t)sk * 12288 + d0 + tx];
    }
    __syncthreads();
    const size_t dstbase = (size_t)(b * 8 + h) * 512 * 2048;
#pragma unroll
    for (int j = 0; j < 4; j++) {
        int d = d0 + ty + j * 8;
        vtf[dstbase + (size_t)d * 2048 + sk0 + tx] = t[tx][ty + j * 8];
    }
}

// =============================================================================
extern "C" void kernel_launch(void* const* d_in, const int* in_sizes, int n_in,
                              void* d_out, int out_size)
{
    const float* x     = (const float*)d_in[0];
    const float* W_sep = (const float*)d_in[1];
    const float* b_sep = (const float*)d_in[2];
    const float* W_mul = (const float*)d_in[3];
    const float* b_mul = (const float*)d_in[4];
    const float* W_res = (const float*)d_in[5];
    const float* b_res = (const float*)d_in[6];
    float* out = (float*)d_out;

    float *xf, *Wst, *Wmf, *Wcf, *beff, *Wrf, *h2f, *sc, *Pf, *Vtf, *apf;
    cudaGetSymbolAddress((void**)&xf,   g_xf);
    cudaGetSymbolAddress((void**)&Wst,  g_Wst);
    cudaGetSymbolAddress((void**)&Wmf,  g_Wmf);
    cudaGetSymbolAddress((void**)&Wcf,  g_Wcf);
    cudaGetSymbolAddress((void**)&beff, g_beff);
    cudaGetSymbolAddress((void**)&Wrf,  g_Wrf);
    cudaGetSymbolAddress((void**)&h2f,  g_h2f);
    cudaGetSymbolAddress((void**)&sc,   g_sc);
    cudaGetSymbolAddress((void**)&Pf,   g_Pf);
    cudaGetSymbolAddress((void**)&Vtf,  g_Vtf);
    cudaGetSymbolAddress((void**)&apf,  g_apf);

    cudaFuncSetAttribute(gemm_tf32, cudaFuncAttributeMaxDynamicSharedMemorySize, SMEM_T32);

    const size_t S = 2048, D = 512, H = 8;

    // (1) round x + W_mul
    round_copy_tf32_2<<<dim3(1024, 2), 256>>>(x, xf, 4096UL * 512,
                                              W_mul, Wmf, 12288UL * 1536);
    // (2) transpose+round W_sep; compute b_eff
    prep_sep<<<816, dim3(32, 8)>>>(W_sep, Wst, W_mul, b_sep, b_mul, beff);

    // (3) Wc = W_mul @ W_sep  -> [12288, 512]  (tf32, rounded out)
    gemm_tf32<<<dim3(4, 96, 1), 128, SMEM_T32>>>(
        Wmf, Wst, Wcf, nullptr,
        1536, 1536, 1536, 512, 1, 0, 0, 0, 0, 0, 0, 1);

    // (4) GEMM2' (PROFILED): h2 = x @ Wc^T + b_eff  [4096 x 12288], K=512
    gemm_tf32<<<dim3(96, 32, 1), 128, SMEM_T32>>>(
        xf, Wcf, h2f, beff,
        512, 512, 512, 12288, 1, 0, 0, 0, 0, 0, 0, 1);

    // (5) QK^T batched: sc = Q @ K^T  [2048 x 2048], K=512
    gemm_tf32<<<dim3(16, 16, 16), 128, SMEM_T32>>>(
        h2f, h2f + 512, sc, nullptr,
        512, 12288, 12288, 2048, 8,
        1536, S * 12288, 1536, S * 12288,
        S * S, H * S * S, 0);

    // (6) softmax(scale * sc) -> P
    softmax_tf32<<<16 * 2048, 256>>>(sc, Pf, 1.0f / sqrtf(512.0f));

    // (7) V^T
    transpose_v<<<dim3(64, 16, 16), dim3(32, 8)>>>(h2f, Vtf);

    // (8) round W_res
    round_copy_tf32<<<512, 256>>>(W_res, Wrf, 512UL * 4096);

    // (9) PV batched: ap = P @ Vt^T  [2048 x 512], K=2048 (rounded out)
    gemm_tf32<<<dim3(4, 16, 16), 128, SMEM_T32>>>(
        Pf, Vtf, apf, nullptr,
        2048, 2048, 2048, 4096, 8,
        S * S, H * S * S, D * S, H * D * S,
        512, S * 4096, 1);

    // (10) GEMM3 split-K=2: partials into sc slabs
    gemm_tf32<<<dim3(4, 32, 2), 128, SMEM_T32>>>(
        apf, Wrf, sc, nullptr,
        2048, 4096, 4096, 512, 2,
        2048, 0, 2048, 0,
        4096UL * 512, 0, 0);

    // (11) out = slab0 + slab1 + b_res
    add_splitk_bias<<<1024, 256>>>(sc, sc + 4096UL * 512, b_res, out, 4096UL * 512);
}

// round 14
// speedup vs baseline: 1.7188x; 1.4980x over previous
#include <cuda_runtime.h>
#include <cuda_fp16.h>
#include <math.h>
#include <stdint.h>

// ===================== scratch (static device arrays) ========================
__device__ __half g_xh [4096UL * 512];
__device__ __half g_Wmh[12288UL * 1536];
__device__ __half g_Wst[512UL * 1536];        // W_sep^T fp16
__device__ __half g_Wch[12288UL * 512];       // Wc = W_mul @ W_sep (fp16)
__device__ float  g_beff[12288];              // b_mul + W_mul @ b_sep (fp32)
__device__ __half g_Wrh[512UL * 4096];
__device__ __half g_h2h[4096UL * 12288];
__device__ float  g_sc [16UL * 2048 * 2048];  // scores fp32; reused as split-K slabs
__device__ __half g_Ph [16UL * 2048 * 2048];
__device__ __half g_Vth[16UL * 512 * 2048];
__device__ __half g_aph[4096UL * 4096];

// ===================== helpers (base-target PTX only) ========================
__device__ __forceinline__ uint32_t smem_u32(const void* p) {
    uint32_t a;
    asm("{ .reg .u64 t; cvta.to.shared.u64 t, %1; cvt.u32.u64 %0, t; }"
        : "=r"(a) : "l"(p));
    return a;
}

__device__ __forceinline__ void cp16(uint32_t s, const void* g) {
    asm volatile("cp.async.cg.shared.global [%0], [%1], 16;"
                 :: "r"(s), "l"(g) : "memory");
}

__device__ __forceinline__ void ldsm4(uint32_t* r, uint32_t addr) {
    asm volatile("ldmatrix.sync.aligned.m8n8.x4.shared.b16 {%0,%1,%2,%3}, [%4];"
                 : "=r"(r[0]), "=r"(r[1]), "=r"(r[2]), "=r"(r[3]) : "r"(addr));
}

__device__ __forceinline__ void mma_f16(float* c, const uint32_t* a, const uint32_t* b) {
    asm volatile(
        "mma.sync.aligned.m16n8k16.row.col.f32.f16.f16.f32 "
        "{%0,%1,%2,%3}, {%4,%5,%6,%7}, {%8,%9}, {%0,%1,%2,%3};"
        : "+f"(c[0]), "+f"(c[1]), "+f"(c[2]), "+f"(c[3])
        : "r"(a[0]), "r"(a[1]), "r"(a[2]), "r"(a[3]), "r"(b[0]), "r"(b[1]));
}

// fp16 tile swizzle: [rows][32 fp16] rows of 64B, 16B chunks (verified R3-R9)
__device__ __forceinline__ uint32_t swz(int row, int chunk) {
    return (uint32_t)(row * 64 + ((chunk ^ ((row >> 1) & 3)) << 4));
}

// ===================== fp16 GEMM (128x128x32, 64x64 warp tiles) ==============
// C = A @ B^T. A: M x K (lda), B: N x K (ldb), fp16 K-major.
// 128 thr (4 warps, 2M x 2N), warp tile 64x64, 3-stage, 2 CTAs/SM.
#define ATILEH 8192                 // 128 x 32 fp16
#define STAGEH (2 * ATILEH)         // 16384
#define NSTAGE 3
#define SMEM_H (NSTAGE * STAGEH)    // 49152

__global__ __launch_bounds__(128, 2)
void gemm_fp16(const __half* __restrict__ A, const __half* __restrict__ B,
               float* __restrict__ Cf, __half* __restrict__ Ch,
               const float* __restrict__ bias,
               int K, int lda, int ldb, int ldc, int NH,
               size_t sAh_, size_t sAb_, size_t sBh_, size_t sBb_,
               size_t sCh_, size_t sCb_)
{
    extern __shared__ char smem[];
    const uint32_t sbase = smem_u32(smem);
    const int tid = threadIdx.x, lane = tid & 31, w = tid >> 5;
    const int wm = w & 1, wn = w >> 1;  // 2M x 2N warps, warp tile 64x64

    const int z = blockIdx.z, hb = z % NH, bb = z / NH;
    const size_t offA = (size_t)hb * sAh_ + (size_t)bb * sAb_;
    const size_t offB = (size_t)hb * sBh_ + (size_t)bb * sBb_;
    const size_t offC = (size_t)hb * sCh_ + (size_t)bb * sCb_;
    const int n0 = blockIdx.x * 128;

    const __half* ag = A + offA + (size_t)(blockIdx.y * 128) * lda;
    const __half* bg = B + offB + (size_t)n0 * ldb;

    float acc[4][8][4];  // 64x64 per warp: 4 m16-tiles x 8 n8-tiles
#pragma unroll
    for (int mt = 0; mt < 4; mt++)
#pragma unroll
        for (int j = 0; j < 8; j++)
#pragma unroll
            for (int q = 0; q < 4; q++) acc[mt][j][q] = 0.0f;

    const int niter = K >> 5;

    auto issue = [&](int it) {
        const uint32_t sb = sbase + (uint32_t)(it % NSTAGE) * STAGEH;
        const int k0 = it << 5;
        // A and B: 512 chunks each -> 4/thread each (128 threads)
#pragma unroll
        for (int q = 0; q < 4; q++) {
            const int idx = tid + q * 128;
            const int r = idx >> 2, c = idx & 3;
            const uint32_t so = swz(r, c);
            cp16(sb + so,          ag + (size_t)r * lda + k0 + c * 8);
            cp16(sb + ATILEH + so, bg + (size_t)r * ldb + k0 + c * 8);
        }
        asm volatile("cp.async.commit_group;" ::: "memory");
    };

    issue(0);
    if (niter > 1) issue(1);

    for (int i = 0; i < niter; i++) {
        if (i + 1 < niter)
            asm volatile("cp.async.wait_group 1;" ::: "memory");
        else
            asm volatile("cp.async.wait_group 0;" ::: "memory");
        __syncthreads();
        if (i + 2 < niter) issue(i + 2);

        const uint32_t sb = sbase + (uint32_t)(i % NSTAGE) * STAGEH;
        const uint32_t sbB = sb + ATILEH;
#pragma unroll
        for (int k16 = 0; k16 < 2; k16++) {
            const int rA = wm * 64 + (lane & 15);
            const int cA = k16 * 2 + (lane >> 4);
            const int rB = wn * 64 + (lane & 7) + ((lane >> 4) << 3);
            const int cB = k16 * 2 + ((lane >> 3) & 1);

            uint32_t af[4][4], bf[4][4];
#pragma unroll
            for (int mt = 0; mt < 4; mt++)
                ldsm4(af[mt], sb + swz(rA + mt * 16, cA));
#pragma unroll
            for (int nt = 0; nt < 4; nt++)
                ldsm4(bf[nt], sbB + swz(rB + nt * 16, cB));
#pragma unroll
            for (int mt = 0; mt < 4; mt++)
#pragma unroll
                for (int nt = 0; nt < 4; nt++) {
                    mma_f16(acc[mt][nt * 2],     af[mt], &bf[nt][0]);
                    mma_f16(acc[mt][nt * 2 + 1], af[mt], &bf[nt][2]);
                }
        }
    }

    // ---------------- epilogue ----------------
    const int gid = lane >> 2, tig = lane & 3;
    const int row0 = blockIdx.y * 128 + wm * 64;
    const int col0 = n0 + wn * 64;
#pragma unroll
    for (int mt = 0; mt < 4; mt++) {
#pragma unroll
        for (int j = 0; j < 8; j++) {
            const int r = row0 + mt * 16 + gid;
            const int c = col0 + j * 8 + tig * 2;
            float b0 = 0.f, b1 = 0.f;
            if (bias) { b0 = __ldg(&bias[c]); b1 = __ldg(&bias[c + 1]); }
            const float v0 = acc[mt][j][0] + b0, v1 = acc[mt][j][1] + b1;
            const float v2 = acc[mt][j][2] + b0, v3 = acc[mt][j][3] + b1;
            const size_t o0 = offC + (size_t)r * ldc + c;
            const size_t o1 = offC + (size_t)(r + 8) * ldc + c;
            if (Ch) {
                *(__half2*)(Ch + o0) = __floats2half2_rn(v0, v1);
                *(__half2*)(Ch + o1) = __floats2half2_rn(v2, v3);
            }
            if (Cf) {
                *(float2*)(Cf + o0) = make_float2(v0, v1);
                *(float2*)(Cf + o1) = make_float2(v2, v3);
            }
        }
    }
}

// ===================== aux kernels ===========================================
__global__ void cvt_half(const float* __restrict__ in, __half* __restrict__ out,
                         size_t n)
{
    size_t i = ((size_t)blockIdx.x * blockDim.x + threadIdx.x) * 4;
    const size_t stride = (size_t)gridDim.x * blockDim.x * 4;
    for (; i < n; i += stride) {
        float4 v = *(const float4*)(in + i);
        *(__half2*)(out + i)     = __floats2half2_rn(v.x, v.y);
        *(__half2*)(out + i + 2) = __floats2half2_rn(v.z, v.w);
    }
}

__global__ void cvt_half_2(const float* __restrict__ in0, __half* __restrict__ out0, size_t n0,
                           const float* __restrict__ in1, __half* __restrict__ out1, size_t n1)
{
    const float* in  = blockIdx.y ? in1  : in0;
    __half*      out = blockIdx.y ? out1 : out0;
    const size_t n   = blockIdx.y ? n1   : n0;
    size_t i = ((size_t)blockIdx.x * blockDim.x + threadIdx.x) * 4;
    const size_t stride = (size_t)gridDim.x * blockDim.x * 4;
    for (; i < n; i += stride) {
        float4 v = *(const float4*)(in + i);
        *(__half2*)(out + i)     = __floats2half2_rn(v.x, v.y);
        *(__half2*)(out + i + 2) = __floats2half2_rn(v.z, v.w);
    }
}

// prep: blocks [0,768): transpose W_sep [1536,512] -> Wst fp16 [512,1536]
//       blocks [768,816): b_eff = b_mul + W_mul @ b_sep (fp32)
__global__ void prep_sep(const float* __restrict__ Wsep, __half* __restrict__ Wst,
                         const float* __restrict__ Wmul, const float* __restrict__ bsep,
                         const float* __restrict__ bmul, float* __restrict__ beff)
{
    const int tx = threadIdx.x, ty = threadIdx.y;  // 32 x 8
    if (blockIdx.x < 768) {
        __shared__ float t[32][33];
        const int e0 = (blockIdx.x % 48) * 32;
        const int d0 = (blockIdx.x / 48) * 32;
#pragma unroll
        for (int j = 0; j < 4; j++)
            t[ty + j * 8][tx] = Wsep[(size_t)(e0 + ty + j * 8) * 512 + d0 + tx];
        __syncthreads();
#pragma unroll
        for (int j = 0; j < 4; j++)
            Wst[(size_t)(d0 + ty + j * 8) * 1536 + e0 + tx] =
                __float2half(t[tx][ty + j * 8]);
    } else {
        const int f = (blockIdx.x - 768) * 256 + ty * 32 + tx;  // 48*256 = 12288
        const float* row = Wmul + (size_t)f * 1536;
        float s = bmul[f];
        for (int e = 0; e < 1536; e++)
            s = fmaf(row[e], __ldg(&bsep[e]), s);
        beff[f] = s;
    }
}

// out = s0 + s1 + bias[col]  (fp32, 512 cols)
__global__ void add_splitk_bias(const float* __restrict__ s0, const float* __restrict__ s1,
                                const float* __restrict__ bias, float* __restrict__ out,
                                size_t n)
{
    size_t i = ((size_t)blockIdx.x * blockDim.x + threadIdx.x) * 4;
    const size_t stride = (size_t)gridDim.x * blockDim.x * 4;
    for (; i < n; i += stride) {
        float4 a = *(const float4*)(s0 + i);
        float4 b = *(const float4*)(s1 + i);
        const int c = (int)(i & 511);
        a.x += b.x + __ldg(&bias[c]);
        a.y += b.y + __ldg(&bias[c + 1]);
        a.z += b.z + __ldg(&bias[c + 2]);
        a.w += b.w + __ldg(&bias[c + 3]);
        *(float4*)(out + i) = a;
    }
}

__global__ void softmax_f16(const float* __restrict__ sc,
                            __half* __restrict__ ph, float scale)
{
    const int tid = threadIdx.x;
    const size_t base = (size_t)blockIdx.x * 2048;
    const float* p = sc + base;
    __shared__ float red[256];

    float v[8];
    float mx = -1e30f;
#pragma unroll
    for (int i = 0; i < 8; i++) {
        v[i] = p[tid + i * 256] * scale;
        mx = fmaxf(mx, v[i]);
    }
    red[tid] = mx;
    __syncthreads();
#pragma unroll
    for (int s = 128; s > 0; s >>= 1) {
        if (tid < s) red[tid] = fmaxf(red[tid], red[tid + s]);
        __syncthreads();
    }
    mx = red[0];
    __syncthreads();

    float sum = 0.0f;
#pragma unroll
    for (int i = 0; i < 8; i++) {
        v[i] = __expf(v[i] - mx);
        sum += v[i];
    }
    red[tid] = sum;
    __syncthreads();
#pragma unroll
    for (int s = 128; s > 0; s >>= 1) {
        if (tid < s) red[tid] += red[tid + s];
        __syncthreads();
    }
    const float inv = 1.0f / red[0];
#pragma unroll
    for (int i = 0; i < 8; i++)
        ph[base + tid + i * 256] = __float2half(v[i] * inv);
}

// V^T per (b,h): Vt[d][sk] = h2h[(b,sk)][h*1536+1024+d]  (fp16)
__global__ void transpose_v(const __half* __restrict__ h2h,
                            __half* __restrict__ vth)
{
    __shared__ __half t[32][34];
    const int z = blockIdx.z, b = z >> 3, h = z & 7;
    const int sk0 = blockIdx.x * 32, d0 = blockIdx.y * 32;
    const int tx = threadIdx.x, ty = threadIdx.y;  // 32 x 8
    const size_t srcbase = (size_t)b * 2048 * 12288 + h * 1536 + 1024;
#pragma unroll
    for (int j = 0; j < 4; j++) {
        int sk = sk0 + ty + j * 8;
        t[ty + j * 8][tx] = h2h[srcbase + (size_t)sk * 12288 + d0 + tx];
    }
    __syncthreads();
    const size_t dstbase = (size_t)(b * 8 + h) * 512 * 2048;
#pragma unroll
    for (int j = 0; j < 4; j++) {
        int d = d0 + ty + j * 8;
        vth[dstbase + (size_t)d * 2048 + sk0 + tx] = t[tx][ty + j * 8];
    }
}

// =============================================================================
extern "C" void kernel_launch(void* const* d_in, const int* in_sizes, int n_in,
                              void* d_out, int out_size)
{
    const float* x     = (const float*)d_in[0];
    const float* W_sep = (const float*)d_in[1];
    const float* b_sep = (const float*)d_in[2];
    const float* W_mul = (const float*)d_in[3];
    const float* b_mul = (const float*)d_in[4];
    const float* W_res = (const float*)d_in[5];
    const float* b_res = (const float*)d_in[6];
    float* out = (float*)d_out;

    __half *xh, *Wmh, *Wst, *Wch, *Wrh, *h2h, *Ph, *Vth, *aph;
    float *beff, *sc;
    cudaGetSymbolAddress((void**)&xh,   g_xh);
    cudaGetSymbolAddress((void**)&Wmh,  g_Wmh);
    cudaGetSymbolAddress((void**)&Wst,  g_Wst);
    cudaGetSymbolAddress((void**)&Wch,  g_Wch);
    cudaGetSymbolAddress((void**)&beff, g_beff);
    cudaGetSymbolAddress((void**)&Wrh,  g_Wrh);
    cudaGetSymbolAddress((void**)&h2h,  g_h2h);
    cudaGetSymbolAddress((void**)&sc,   g_sc);
    cudaGetSymbolAddress((void**)&Ph,   g_Ph);
    cudaGetSymbolAddress((void**)&Vth,  g_Vth);
    cudaGetSymbolAddress((void**)&aph,  g_aph);

    cudaFuncSetAttribute(gemm_fp16, cudaFuncAttributeMaxDynamicSharedMemorySize, SMEM_H);

    const size_t S = 2048, D = 512, H = 8;

    // (1) convert x + W_mul to fp16
    cvt_half_2<<<dim3(1024, 2), 256>>>(x, xh, 4096UL * 512,
                                       W_mul, Wmh, 12288UL * 1536);
    // (2) transpose W_sep -> fp16; compute b_eff
    prep_sep<<<816, dim3(32, 8)>>>(W_sep, Wst, W_mul, b_sep, b_mul, beff);

    // (3) Wc = W_mul @ W_sep -> fp16 [12288, 512]
    gemm_fp16<<<dim3(4, 96, 1), 128, SMEM_H>>>(
        Wmh, Wst, nullptr, Wch, nullptr,
        1536, 1536, 1536, 512, 1, 0, 0, 0, 0, 0, 0);

    // (4) GEMM2' (PROFILED): h2 = x @ Wc^T + b_eff  [4096 x 12288], K=512
    gemm_fp16<<<dim3(96, 32, 1), 128, SMEM_H>>>(
        xh, Wch, nullptr, h2h, beff,
        512, 512, 512, 12288, 1, 0, 0, 0, 0, 0, 0);

    // (5) QK^T batched: sc = Q @ K^T  [2048 x 2048], K=512 (fp32 out)
    gemm_fp16<<<dim3(16, 16, 16), 128, SMEM_H>>>(
        h2h, h2h + 512, sc, nullptr, nullptr,
        512, 12288, 12288, 2048, 8,
        1536, S * 12288, 1536, S * 12288,
        S * S, H * S * S);

    // (6) softmax(scale * sc) -> P (fp16)
    softmax_f16<<<16 * 2048, 256>>>(sc, Ph, 1.0f / sqrtf(512.0f));

    // (7) V^T (fp16)
    transpose_v<<<dim3(64, 16, 16), dim3(32, 8)>>>(h2h, Vth);

    // (8) convert W_res to fp16
    cvt_half<<<512, 256>>>(W_res, Wrh, 512UL * 4096);

    // (9) PV batched: ap = P @ Vt^T  [2048 x 512], K=2048 (fp16 out)
    gemm_fp16<<<dim3(4, 16, 16), 128, SMEM_H>>>(
        Ph, Vth, nullptr, aph, nullptr,
        2048, 2048, 2048, 4096, 8,
        S * S, H * S * S, D * S, H * D * S,
        512, S * 4096);

    // (10) GEMM3 split-K=2: fp32 partials into sc slabs
    gemm_fp16<<<dim3(4, 32, 2), 128, SMEM_H>>>(
        aph, Wrh, sc, nullptr, nullptr,
        2048, 4096, 4096, 512, 2,
        2048, 0, 2048, 0,
        4096UL * 512, 0);

    // (11) out = slab0 + slab1 + b_res
    add_splitk_bias<<<1024, 256>>>(sc, sc + 4096UL * 512, b_res, out, 4096UL * 512);
}

// round 15
// speedup vs baseline: 2.2363x; 1.3011x over previous
#include <cuda_runtime.h>
#include <cuda_fp16.h>
#include <math.h>
#include <stdint.h>

// ===================== scratch (static device arrays) ========================
__device__ __half g_xh [4096UL * 512];
__device__ __half g_Wmh[12288UL * 1536];
__device__ __half g_Wst[512UL * 1536];        // W_sep^T fp16
__device__ __half g_Wch[12288UL * 512];       // Wc = W_mul @ W_sep (fp16)
__device__ float  g_beff[12288];              // b_mul + W_mul @ b_sep (fp32)
__device__ __half g_Wrh[512UL * 4096];
__device__ __half g_h2h[4096UL * 12288];
__device__ __half g_sch[16UL * 2048 * 2048];  // scores fp16
__device__ float  g_sk [2UL * 4096 * 512];    // split-K slabs fp32
__device__ __half g_Ph [16UL * 2048 * 2048];
__device__ __half g_Vth[16UL * 512 * 2048];
__device__ __half g_aph[4096UL * 4096];

// ===================== helpers (base-target PTX only) ========================
__device__ __forceinline__ uint32_t smem_u32(const void* p) {
    uint32_t a;
    asm("{ .reg .u64 t; cvta.to.shared.u64 t, %1; cvt.u32.u64 %0, t; }"
        : "=r"(a) : "l"(p));
    return a;
}

__device__ __forceinline__ void cp16(uint32_t s, const void* g) {
    asm volatile("cp.async.cg.shared.global [%0], [%1], 16;"
                 :: "r"(s), "l"(g) : "memory");
}

__device__ __forceinline__ void ldsm4(uint32_t* r, uint32_t addr) {
    asm volatile("ldmatrix.sync.aligned.m8n8.x4.shared.b16 {%0,%1,%2,%3}, [%4];"
                 : "=r"(r[0]), "=r"(r[1]), "=r"(r[2]), "=r"(r[3]) : "r"(addr));
}

__device__ __forceinline__ void mma_f16(float* c, const uint32_t* a, const uint32_t* b) {
    asm volatile(
        "mma.sync.aligned.m16n8k16.row.col.f32.f16.f16.f32 "
        "{%0,%1,%2,%3}, {%4,%5,%6,%7}, {%8,%9}, {%0,%1,%2,%3};"
        : "+f"(c[0]), "+f"(c[1]), "+f"(c[2]), "+f"(c[3])
        : "r"(a[0]), "r"(a[1]), "r"(a[2]), "r"(a[3]), "r"(b[0]), "r"(b[1]));
}

// fp16 tile swizzle: [rows][32 fp16] rows of 64B, 16B chunks
__device__ __forceinline__ uint32_t swz(int row, int chunk) {
    return (uint32_t)(row * 64 + ((chunk ^ ((row >> 1) & 3)) << 4));
}

// ===================== fp16 GEMM (128x128x32, 64x64 warp tiles) ==============
// C = A @ B^T. 128 thr (4 warps 2x2), 4-stage cp.async, 2 CTAs/SM.
#define ATILEH 8192                 // 128 x 32 fp16
#define STAGEH (2 * ATILEH)         // 16384
#define NSTAGE 4
#define SMEM_H (NSTAGE * STAGEH)    // 65536

__global__ __launch_bounds__(128, 2)
void gemm_fp16(const __half* __restrict__ A, const __half* __restrict__ B,
               float* __restrict__ Cf, __half* __restrict__ Ch,
               const float* __restrict__ bias,
               int K, int lda, int ldb, int ldc, int NH,
               size_t sAh_, size_t sAb_, size_t sBh_, size_t sBb_,
               size_t sCh_, size_t sCb_)
{
    extern __shared__ char smem[];
    const uint32_t sbase = smem_u32(smem);
    const int tid = threadIdx.x, lane = tid & 31, w = tid >> 5;
    const int wm = w & 1, wn = w >> 1;

    const int z = blockIdx.z, hb = z % NH, bb = z / NH;
    const size_t offA = (size_t)hb * sAh_ + (size_t)bb * sAb_;
    const size_t offB = (size_t)hb * sBh_ + (size_t)bb * sBb_;
    const size_t offC = (size_t)hb * sCh_ + (size_t)bb * sCb_;
    const int n0 = blockIdx.x * 128;

    const __half* ag = A + offA + (size_t)(blockIdx.y * 128) * lda;
    const __half* bg = B + offB + (size_t)n0 * ldb;

    float acc[4][8][4];
#pragma unroll
    for (int mt = 0; mt < 4; mt++)
#pragma unroll
        for (int j = 0; j < 8; j++)
#pragma unroll
            for (int q = 0; q < 4; q++) acc[mt][j][q] = 0.0f;

    const int niter = K >> 5;

    auto issue = [&](int it) {
        const uint32_t sb = sbase + (uint32_t)(it % NSTAGE) * STAGEH;
        const int k0 = it << 5;
#pragma unroll
        for (int q = 0; q < 4; q++) {
            const int idx = tid + q * 128;
            const int r = idx >> 2, c = idx & 3;
            const uint32_t so = swz(r, c);
            cp16(sb + so,          ag + (size_t)r * lda + k0 + c * 8);
            cp16(sb + ATILEH + so, bg + (size_t)r * ldb + k0 + c * 8);
        }
        asm volatile("cp.async.commit_group;" ::: "memory");
    };

    issue(0);
    if (niter > 1) issue(1);
    if (niter > 2) issue(2);

    for (int i = 0; i < niter; i++) {
        const int rem = niter - 1 - i;  // groups still in flight beyond current
        if (rem >= 2)
            asm volatile("cp.async.wait_group 2;" ::: "memory");
        else if (rem == 1)
            asm volatile("cp.async.wait_group 1;" ::: "memory");
        else
            asm volatile("cp.async.wait_group 0;" ::: "memory");
        __syncthreads();
        if (i + 3 < niter) issue(i + 3);

        const uint32_t sb = sbase + (uint32_t)(i % NSTAGE) * STAGEH;
        const uint32_t sbB = sb + ATILEH;
#pragma unroll
        for (int k16 = 0; k16 < 2; k16++) {
            const int rA = wm * 64 + (lane & 15);
            const int cA = k16 * 2 + (lane >> 4);
            const int rB = wn * 64 + (lane & 7) + ((lane >> 4) << 3);
            const int cB = k16 * 2 + ((lane >> 3) & 1);

            uint32_t af[4][4], bf[4][4];
#pragma unroll
            for (int mt = 0; mt < 4; mt++)
                ldsm4(af[mt], sb + swz(rA + mt * 16, cA));
#pragma unroll
            for (int nt = 0; nt < 4; nt++)
                ldsm4(bf[nt], sbB + swz(rB + nt * 16, cB));
#pragma unroll
            for (int mt = 0; mt < 4; mt++)
#pragma unroll
                for (int nt = 0; nt < 4; nt++) {
                    mma_f16(acc[mt][nt * 2],     af[mt], &bf[nt][0]);
                    mma_f16(acc[mt][nt * 2 + 1], af[mt], &bf[nt][2]);
                }
        }
    }

    // ---------------- epilogue ----------------
    const int gid = lane >> 2, tig = lane & 3;
    const int row0 = blockIdx.y * 128 + wm * 64;
    const int col0 = n0 + wn * 64;
#pragma unroll
    for (int mt = 0; mt < 4; mt++) {
#pragma unroll
        for (int j = 0; j < 8; j++) {
            const int r = row0 + mt * 16 + gid;
            const int c = col0 + j * 8 + tig * 2;
            float b0 = 0.f, b1 = 0.f;
            if (bias) { b0 = __ldg(&bias[c]); b1 = __ldg(&bias[c + 1]); }
            const float v0 = acc[mt][j][0] + b0, v1 = acc[mt][j][1] + b1;
            const float v2 = acc[mt][j][2] + b0, v3 = acc[mt][j][3] + b1;
            const size_t o0 = offC + (size_t)r * ldc + c;
            const size_t o1 = offC + (size_t)(r + 8) * ldc + c;
            if (Ch) {
                *(__half2*)(Ch + o0) = __floats2half2_rn(v0, v1);
                *(__half2*)(Ch + o1) = __floats2half2_rn(v2, v3);
            }
            if (Cf) {
                *(float2*)(Cf + o0) = make_float2(v0, v1);
                *(float2*)(Cf + o1) = make_float2(v2, v3);
            }
        }
    }
}

// ===================== aux kernels ===========================================
__global__ void cvt_half(const float* __restrict__ in, __half* __restrict__ out,
                         size_t n)
{
    size_t i = ((size_t)blockIdx.x * blockDim.x + threadIdx.x) * 4;
    const size_t stride = (size_t)gridDim.x * blockDim.x * 4;
    for (; i < n; i += stride) {
        float4 v = *(const float4*)(in + i);
        *(__half2*)(out + i)     = __floats2half2_rn(v.x, v.y);
        *(__half2*)(out + i + 2) = __floats2half2_rn(v.z, v.w);
    }
}

__global__ void cvt_half_2(const float* __restrict__ in0, __half* __restrict__ out0, size_t n0,
                           const float* __restrict__ in1, __half* __restrict__ out1, size_t n1)
{
    const float* in  = blockIdx.y ? in1  : in0;
    __half*      out = blockIdx.y ? out1 : out0;
    const size_t n   = blockIdx.y ? n1   : n0;
    size_t i = ((size_t)blockIdx.x * blockDim.x + threadIdx.x) * 4;
    const size_t stride = (size_t)gridDim.x * blockDim.x * 4;
    for (; i < n; i += stride) {
        float4 v = *(const float4*)(in + i);
        *(__half2*)(out + i)     = __floats2half2_rn(v.x, v.y);
        *(__half2*)(out + i + 2) = __floats2half2_rn(v.z, v.w);
    }
}

// prep: blocks [0,768): transpose W_sep [1536,512] -> Wst fp16 [512,1536]
//       blocks [768,864): b_eff = b_mul + W_mul @ b_sep (warp-per-row, coalesced)
__global__ void prep_sep(const float* __restrict__ Wsep, __half* __restrict__ Wst,
                         const float* __restrict__ Wmul, const float* __restrict__ bsep,
                         const float* __restrict__ bmul, float* __restrict__ beff)
{
    if (blockIdx.x < 768) {
        __shared__ float t[32][33];
        const int tx = threadIdx.x & 31, ty = threadIdx.x >> 5;  // 32 x 8
        const int e0 = (blockIdx.x % 48) * 32;
        const int d0 = (blockIdx.x / 48) * 32;
#pragma unroll
        for (int j = 0; j < 4; j++)
            t[ty + j * 8][tx] = Wsep[(size_t)(e0 + ty + j * 8) * 512 + d0 + tx];
        __syncthreads();
#pragma unroll
        for (int j = 0; j < 4; j++)
            Wst[(size_t)(d0 + ty + j * 8) * 1536 + e0 + tx] =
                __float2half(t[tx][ty + j * 8]);
    } else {
        // 96 blocks x 8 warps = 768 warps; each warp does 16 rows
        const int lane = threadIdx.x & 31, wrp = threadIdx.x >> 5;
        const int wglobal = (blockIdx.x - 768) * 8 + wrp;  // 0..767
#pragma unroll 1
        for (int t = 0; t < 16; t++) {
            const int f = wglobal * 16 + t;
            const float* row = Wmul + (size_t)f * 1536;
            float s = 0.0f;
            for (int e = lane; e < 1536; e += 32)
                s = fmaf(row[e], __ldg(&bsep[e]), s);
#pragma unroll
            for (int o = 16; o > 0; o >>= 1)
                s += __shfl_down_sync(0xFFFFFFFF, s, o);
            if (lane == 0) beff[f] = s + bmul[f];
        }
    }
}

// out = s0 + s1 + bias[col]  (fp32, 512 cols)
__global__ void add_splitk_bias(const float* __restrict__ s0, const float* __restrict__ s1,
                                const float* __restrict__ bias, float* __restrict__ out,
                                size_t n)
{
    size_t i = ((size_t)blockIdx.x * blockDim.x + threadIdx.x) * 4;
    const size_t stride = (size_t)gridDim.x * blockDim.x * 4;
    for (; i < n; i += stride) {
        float4 a = *(const float4*)(s0 + i);
        float4 b = *(const float4*)(s1 + i);
        const int c = (int)(i & 511);
        a.x += b.x + __ldg(&bias[c]);
        a.y += b.y + __ldg(&bias[c + 1]);
        a.z += b.z + __ldg(&bias[c + 2]);
        a.w += b.w + __ldg(&bias[c + 3]);
        *(float4*)(out + i) = a;
    }
}

// softmax over fp16 scores -> fp16 P
__global__ void softmax_f16(const __half* __restrict__ sc,
                            __half* __restrict__ ph, float scale)
{
    const int tid = threadIdx.x;
    const size_t base = (size_t)blockIdx.x * 2048;
    __shared__ float red[256];

    float v[8];
    float mx = -1e30f;
#pragma unroll
    for (int i = 0; i < 8; i += 2) {
        __half2 h2 = *(const __half2*)(sc + base + tid * 2 + i * 256);
        float2 f2 = __half22float2(h2);
        v[i]     = f2.x * scale;
        v[i + 1] = f2.y * scale;
        mx = fmaxf(mx, fmaxf(v[i], v[i + 1]));
    }
    red[tid] = mx;
    __syncthreads();
#pragma unroll
    for (int s = 128; s > 0; s >>= 1) {
        if (tid < s) red[tid] = fmaxf(red[tid], red[tid + s]);
        __syncthreads();
    }
    mx = red[0];
    __syncthreads();

    float sum = 0.0f;
#pragma unroll
    for (int i = 0; i < 8; i++) {
        v[i] = __expf(v[i] - mx);
        sum += v[i];
    }
    red[tid] = sum;
    __syncthreads();
#pragma unroll
    for (int s = 128; s > 0; s >>= 1) {
        if (tid < s) red[tid] += red[tid + s];
        __syncthreads();
    }
    const float inv = 1.0f / red[0];
#pragma unroll
    for (int i = 0; i < 8; i += 2)
        *(__half2*)(ph + base + tid * 2 + i * 256) =
            __floats2half2_rn(v[i] * inv, v[i + 1] * inv);
}

// V^T per (b,h): Vt[d][sk] = h2h[(b,sk)][h*1536+1024+d]  (fp16)
__global__ void transpose_v(const __half* __restrict__ h2h,
                            __half* __restrict__ vth)
{
    __shared__ __half t[32][34];
    const int z = blockIdx.z, b = z >> 3, h = z & 7;
    const int sk0 = blockIdx.x * 32, d0 = blockIdx.y * 32;
    const int tx = threadIdx.x, ty = threadIdx.y;  // 32 x 8
    const size_t srcbase = (size_t)b * 2048 * 12288 + h * 1536 + 1024;
#pragma unroll
    for (int j = 0; j < 4; j++) {
        int sk = sk0 + ty + j * 8;
        t[ty + j * 8][tx] = h2h[srcbase + (size_t)sk * 12288 + d0 + tx];
    }
    __syncthreads();
    const size_t dstbase = (size_t)(b * 8 + h) * 512 * 2048;
#pragma unroll
    for (int j = 0; j < 4; j++) {
        int d = d0 + ty + j * 8;
        vth[dstbase + (size_t)d * 2048 + sk0 + tx] = t[tx][ty + j * 8];
    }
}

// =============================================================================
extern "C" void kernel_launch(void* const* d_in, const int* in_sizes, int n_in,
                              void* d_out, int out_size)
{
    const float* x     = (const float*)d_in[0];
    const float* W_sep = (const float*)d_in[1];
    const float* b_sep = (const float*)d_in[2];
    const float* W_mul = (const float*)d_in[3];
    const float* b_mul = (const float*)d_in[4];
    const float* W_res = (const float*)d_in[5];
    const float* b_res = (const float*)d_in[6];
    float* out = (float*)d_out;

    __half *xh, *Wmh, *Wst, *Wch, *Wrh, *h2h, *sch, *Ph, *Vth, *aph;
    float *beff, *sk;
    cudaGetSymbolAddress((void**)&xh,   g_xh);
    cudaGetSymbolAddress((void**)&Wmh,  g_Wmh);
    cudaGetSymbolAddress((void**)&Wst,  g_Wst);
    cudaGetSymbolAddress((void**)&Wch,  g_Wch);
    cudaGetSymbolAddress((void**)&beff, g_beff);
    cudaGetSymbolAddress((void**)&Wrh,  g_Wrh);
    cudaGetSymbolAddress((void**)&h2h,  g_h2h);
    cudaGetSymbolAddress((void**)&sch,  g_sch);
    cudaGetSymbolAddress((void**)&sk,   g_sk);
    cudaGetSymbolAddress((void**)&Ph,   g_Ph);
    cudaGetSymbolAddress((void**)&Vth,  g_Vth);
    cudaGetSymbolAddress((void**)&aph,  g_aph);

    cudaFuncSetAttribute(gemm_fp16, cudaFuncAttributeMaxDynamicSharedMemorySize, SMEM_H);

    const size_t S = 2048, D = 512, H = 8;

    // (1) convert x + W_mul to fp16
    cvt_half_2<<<dim3(1024, 2), 256>>>(x, xh, 4096UL * 512,
                                       W_mul, Wmh, 12288UL * 1536);
    // (2) transpose W_sep -> fp16; b_eff (coalesced warp-reduce)
    prep_sep<<<864, 256>>>(W_sep, Wst, W_mul, b_sep, b_mul, beff);

    // (3) Wc = W_mul @ W_sep -> fp16 [12288, 512]
    gemm_fp16<<<dim3(4, 96, 1), 128, SMEM_H>>>(
        Wmh, Wst, nullptr, Wch, nullptr,
        1536, 1536, 1536, 512, 1, 0, 0, 0, 0, 0, 0);

    // (4) GEMM2' (PROFILED): h2 = x @ Wc^T + b_eff  [4096 x 12288], K=512
    gemm_fp16<<<dim3(96, 32, 1), 128, SMEM_H>>>(
        xh, Wch, nullptr, h2h, beff,
        512, 512, 512, 12288, 1, 0, 0, 0, 0, 0, 0);

    // (5) QK^T batched: sch = Q @ K^T  [2048 x 2048], K=512 (fp16 out)
    gemm_fp16<<<dim3(16, 16, 16), 128, SMEM_H>>>(
        h2h, h2h + 512, nullptr, sch, nullptr,
        512, 12288, 12288, 2048, 8,
        1536, S * 12288, 1536, S * 12288,
        S * S, H * S * S);

    // (6) softmax(scale * sch) -> P (fp16)
    softmax_f16<<<16 * 2048, 256>>>(sch, Ph, 1.0f / sqrtf(512.0f));

    // (7) V^T (fp16)
    transpose_v<<<dim3(64, 16, 16), dim3(32, 8)>>>(h2h, Vth);

    // (8) convert W_res to fp16
    cvt_half<<<512, 256>>>(W_res, Wrh, 512UL * 4096);

    // (9) PV batched: ap = P @ Vt^T  [2048 x 512], K=2048 (fp16 out)
    gemm_fp16<<<dim3(4, 16, 16), 128, SMEM_H>>>(
        Ph, Vth, nullptr, aph, nullptr,
        2048, 2048, 2048, 4096, 8,
        S * S, H * S * S, D * S, H * D * S,
        512, S * 4096);

    // (10) GEMM3 split-K=2: fp32 partials into sk slabs
    gemm_fp16<<<dim3(4, 32, 2), 128, SMEM_H>>>(
        aph, Wrh, sk, nullptr, nullptr,
        2048, 4096, 4096, 512, 2,
        2048, 0, 2048, 0,
        4096UL * 512, 0);

    // (11) out = slab0 + slab1 + b_res
    add_splitk_bias<<<1024, 256>>>(sk, sk + 4096UL * 512, b_res, out, 4096UL * 512);
}

// round 16
// speedup vs baseline: 2.4401x; 1.0911x over previous
#include <cuda_runtime.h>
#include <cuda_fp16.h>
#include <math.h>
#include <stdint.h>

// ===================== scratch (static device arrays) ========================
__device__ __half g_xh [4096UL * 512];
__device__ __half g_Wmh[12288UL * 1536];
__device__ __half g_Wst[512UL * 1536];        // W_sep^T fp16
__device__ __half g_Wch[12288UL * 512];       // Wc = W_mul @ W_sep (fp16)
__device__ float  g_beff[12288];              // b_mul + W_mul @ b_sep (fp32)
__device__ __half g_Wrh[512UL * 4096];
__device__ __half g_h2h[4096UL * 12288];
__device__ float  g_Z  [16UL * 2048];         // softmax row sums
__device__ float  g_sk [2UL * 4096 * 512];    // split-K slabs fp32
__device__ __half g_Ph [16UL * 2048 * 2048];  // unnormalized exp scores fp16
__device__ __half g_Vth[16UL * 512 * 2048];
__device__ __half g_aph[4096UL * 4096];

// ===================== helpers (base-target PTX only) ========================
__device__ __forceinline__ uint32_t smem_u32(const void* p) {
    uint32_t a;
    asm("{ .reg .u64 t; cvta.to.shared.u64 t, %1; cvt.u32.u64 %0, t; }"
        : "=r"(a) : "l"(p));
    return a;
}

__device__ __forceinline__ void cp16(uint32_t s, const void* g) {
    asm volatile("cp.async.cg.shared.global [%0], [%1], 16;"
                 :: "r"(s), "l"(g) : "memory");
}

__device__ __forceinline__ void ldsm4(uint32_t* r, uint32_t addr) {
    asm volatile("ldmatrix.sync.aligned.m8n8.x4.shared.b16 {%0,%1,%2,%3}, [%4];"
                 : "=r"(r[0]), "=r"(r[1]), "=r"(r[2]), "=r"(r[3]) : "r"(addr));
}

__device__ __forceinline__ void mma_f16(float* c, const uint32_t* a, const uint32_t* b) {
    asm volatile(
        "mma.sync.aligned.m16n8k16.row.col.f32.f16.f16.f32 "
        "{%0,%1,%2,%3}, {%4,%5,%6,%7}, {%8,%9}, {%0,%1,%2,%3};"
        : "+f"(c[0]), "+f"(c[1]), "+f"(c[2]), "+f"(c[3])
        : "r"(a[0]), "r"(a[1]), "r"(a[2]), "r"(a[3]), "r"(b[0]), "r"(b[1]));
}

// fp16 tile swizzle: [rows][32 fp16] rows of 64B, 16B chunks
__device__ __forceinline__ uint32_t swz(int row, int chunk) {
    return (uint32_t)(row * 64 + ((chunk ^ ((row >> 1) & 3)) << 4));
}

// ===================== fp16 GEMM (128x128x32, 64x64 warp tiles) ==============
// C = A @ B^T. 128 thr (4 warps 2x2), 4-stage cp.async, 2 CTAs/SM.
// EPI: 0 = bias + write Cf(fp32)/Ch(fp16)
//      1 = softmax-producer: Ch = exp(min(acc*scale,11)); atomicAdd row sums Z
//      2 = normalizer-consumer: Ch = acc * (1/Z[row])
#define ATILEH 8192
#define STAGEH (2 * ATILEH)         // 16384
#define NSTAGE 4
#define SMEM_H (NSTAGE * STAGEH)    // 65536

template <int EPI>
__global__ __launch_bounds__(128, 2)
void gemm_fp16(const __half* __restrict__ A, const __half* __restrict__ B,
               float* __restrict__ Cf, __half* __restrict__ Ch,
               const float* __restrict__ bias,
               int K, int lda, int ldb, int ldc, int NH,
               size_t sAh_, size_t sAb_, size_t sBh_, size_t sBb_,
               size_t sCh_, size_t sCb_, float scale, float* __restrict__ Z)
{
    extern __shared__ char smem[];
    const uint32_t sbase = smem_u32(smem);
    const int tid = threadIdx.x, lane = tid & 31, w = tid >> 5;
    const int wm = w & 1, wn = w >> 1;

    const int z = blockIdx.z, hb = z % NH, bb = z / NH;
    const size_t offA = (size_t)hb * sAh_ + (size_t)bb * sAb_;
    const size_t offB = (size_t)hb * sBh_ + (size_t)bb * sBb_;
    const size_t offC = (size_t)hb * sCh_ + (size_t)bb * sCb_;
    const int n0 = blockIdx.x * 128;

    const __half* ag = A + offA + (size_t)(blockIdx.y * 128) * lda;
    const __half* bg = B + offB + (size_t)n0 * ldb;

    float acc[4][8][4];
#pragma unroll
    for (int mt = 0; mt < 4; mt++)
#pragma unroll
        for (int j = 0; j < 8; j++)
#pragma unroll
            for (int q = 0; q < 4; q++) acc[mt][j][q] = 0.0f;

    const int niter = K >> 5;

    auto issue = [&](int it) {
        const uint32_t sb = sbase + (uint32_t)(it % NSTAGE) * STAGEH;
        const int k0 = it << 5;
#pragma unroll
        for (int q = 0; q < 4; q++) {
            const int idx = tid + q * 128;
            const int r = idx >> 2, c = idx & 3;
            const uint32_t so = swz(r, c);
            cp16(sb + so,          ag + (size_t)r * lda + k0 + c * 8);
            cp16(sb + ATILEH + so, bg + (size_t)r * ldb + k0 + c * 8);
        }
        asm volatile("cp.async.commit_group;" ::: "memory");
    };

    issue(0);
    if (niter > 1) issue(1);
    if (niter > 2) issue(2);

    for (int i = 0; i < niter; i++) {
        const int rem = niter - 1 - i;
        if (rem >= 2)
            asm volatile("cp.async.wait_group 2;" ::: "memory");
        else if (rem == 1)
            asm volatile("cp.async.wait_group 1;" ::: "memory");
        else
            asm volatile("cp.async.wait_group 0;" ::: "memory");
        __syncthreads();
        if (i + 3 < niter) issue(i + 3);

        const uint32_t sb = sbase + (uint32_t)(i % NSTAGE) * STAGEH;
        const uint32_t sbB = sb + ATILEH;
#pragma unroll
        for (int k16 = 0; k16 < 2; k16++) {
            const int rA = wm * 64 + (lane & 15);
            const int cA = k16 * 2 + (lane >> 4);
            const int rB = wn * 64 + (lane & 7) + ((lane >> 4) << 3);
            const int cB = k16 * 2 + ((lane >> 3) & 1);

            uint32_t af[4][4], bf[4][4];
#pragma unroll
            for (int mt = 0; mt < 4; mt++)
                ldsm4(af[mt], sb + swz(rA + mt * 16, cA));
#pragma unroll
            for (int nt = 0; nt < 4; nt++)
                ldsm4(bf[nt], sbB + swz(rB + nt * 16, cB));
#pragma unroll
            for (int mt = 0; mt < 4; mt++)
#pragma unroll
                for (int nt = 0; nt < 4; nt++) {
                    mma_f16(acc[mt][nt * 2],     af[mt], &bf[nt][0]);
                    mma_f16(acc[mt][nt * 2 + 1], af[mt], &bf[nt][2]);
                }
        }
    }

    // ---------------- epilogue ----------------
    const int gid = lane >> 2, tig = lane & 3;
    const int row0 = blockIdx.y * 128 + wm * 64;
    const int col0 = n0 + wn * 64;
#pragma unroll
    for (int mt = 0; mt < 4; mt++) {
        const int r = row0 + mt * 16 + gid;
        float sum_r = 0.0f, sum_r8 = 0.0f;
        float iz0 = 1.0f, iz1 = 1.0f;
        if (EPI == 2) {
            iz0 = 1.0f / __ldg(&Z[(size_t)z * 2048 + r]);
            iz1 = 1.0f / __ldg(&Z[(size_t)z * 2048 + r + 8]);
        }
#pragma unroll
        for (int j = 0; j < 8; j++) {
            const int c = col0 + j * 8 + tig * 2;
            float v0 = acc[mt][j][0], v1 = acc[mt][j][1];
            float v2 = acc[mt][j][2], v3 = acc[mt][j][3];
            const size_t o0 = offC + (size_t)r * ldc + c;
            const size_t o1 = offC + (size_t)(r + 8) * ldc + c;
            if (EPI == 0) {
                float b0 = 0.f, b1 = 0.f;
                if (bias) { b0 = __ldg(&bias[c]); b1 = __ldg(&bias[c + 1]); }
                v0 += b0; v1 += b1; v2 += b0; v3 += b1;
                if (Ch) {
                    *(__half2*)(Ch + o0) = __floats2half2_rn(v0, v1);
                    *(__half2*)(Ch + o1) = __floats2half2_rn(v2, v3);
                }
                if (Cf) {
                    *(float2*)(Cf + o0) = make_float2(v0, v1);
                    *(float2*)(Cf + o1) = make_float2(v2, v3);
                }
            } else if (EPI == 1) {
                v0 = __expf(fminf(v0 * scale, 11.0f));
                v1 = __expf(fminf(v1 * scale, 11.0f));
                v2 = __expf(fminf(v2 * scale, 11.0f));
                v3 = __expf(fminf(v3 * scale, 11.0f));
                sum_r  += v0 + v1;
                sum_r8 += v2 + v3;
                *(__half2*)(Ch + o0) = __floats2half2_rn(v0, v1);
                *(__half2*)(Ch + o1) = __floats2half2_rn(v2, v3);
            } else {  // EPI == 2
                *(__half2*)(Ch + o0) = __floats2half2_rn(v0 * iz0, v1 * iz0);
                *(__half2*)(Ch + o1) = __floats2half2_rn(v2 * iz1, v3 * iz1);
            }
        }
        if (EPI == 1) {
            // reduce across the 4 col-threads of this row (lanes gid*4 + tig)
            sum_r  += __shfl_xor_sync(0xFFFFFFFF, sum_r, 1);
            sum_r  += __shfl_xor_sync(0xFFFFFFFF, sum_r, 2);
            sum_r8 += __shfl_xor_sync(0xFFFFFFFF, sum_r8, 1);
            sum_r8 += __shfl_xor_sync(0xFFFFFFFF, sum_r8, 2);
            if (tig == 0) {
                atomicAdd(&Z[(size_t)z * 2048 + r],     sum_r);
                atomicAdd(&Z[(size_t)z * 2048 + r + 8], sum_r8);
            }
        }
    }
}

// ===================== mega-prep kernel ======================================
// block ranges: [0,2048) x->fp16; [2048,20480) W_mul->fp16;
// [20480,22528) W_res->fp16; [22528,23296) W_sep transpose->fp16;
// [23296,23392) b_eff; [23392,23424) zero Z.
#define PB0 2048
#define PB1 20480
#define PB2 22528
#define PB3 23296
#define PB4 23392
#define PB5 23424

__global__ void prep_all(const float* __restrict__ x,     __half* __restrict__ xh,
                         const float* __restrict__ Wmul,  __half* __restrict__ Wmh,
                         const float* __restrict__ Wres,  __half* __restrict__ Wrh,
                         const float* __restrict__ Wsep,  __half* __restrict__ Wst,
                         const float* __restrict__ bsep,  const float* __restrict__ bmul,
                         float* __restrict__ beff, float* __restrict__ Z)
{
    const int b = blockIdx.x, tid = threadIdx.x;
    if (b < PB2) {
        const float* in;
        __half* out;
        size_t base;
        if (b < PB0)      { in = x;    out = xh;  base = (size_t)b * 1024; }
        else if (b < PB1) { in = Wmul; out = Wmh; base = (size_t)(b - PB0) * 1024; }
        else              { in = Wres; out = Wrh; base = (size_t)(b - PB1) * 1024; }
        const size_t i = base + (size_t)tid * 4;
        float4 v = *(const float4*)(in + i);
        *(__half2*)(out + i)     = __floats2half2_rn(v.x, v.y);
        *(__half2*)(out + i + 2) = __floats2half2_rn(v.z, v.w);
    } else if (b < PB3) {
        __shared__ float t[32][33];
        const int bb = b - PB2;
        const int tx = tid & 31, ty = tid >> 5;
        const int e0 = (bb % 48) * 32;
        const int d0 = (bb / 48) * 32;
#pragma unroll
        for (int j = 0; j < 4; j++)
            t[ty + j * 8][tx] = Wsep[(size_t)(e0 + ty + j * 8) * 512 + d0 + tx];
        __syncthreads();
#pragma unroll
        for (int j = 0; j < 4; j++)
            Wst[(size_t)(d0 + ty + j * 8) * 1536 + e0 + tx] =
                __float2half(t[tx][ty + j * 8]);
    } else if (b < PB4) {
        const int lane = tid & 31, wrp = tid >> 5;
        const int wglobal = (b - PB3) * 8 + wrp;  // 0..767
#pragma unroll 1
        for (int t = 0; t < 16; t++) {
            const int f = wglobal * 16 + t;
            const float* row = Wmul + (size_t)f * 1536;
            float s = 0.0f;
            for (int e = lane; e < 1536; e += 32)
                s = fmaf(row[e], __ldg(&bsep[e]), s);
#pragma unroll
            for (int o = 16; o > 0; o >>= 1)
                s += __shfl_down_sync(0xFFFFFFFF, s, o);
            if (lane == 0) beff[f] = s + bmul[f];
        }
    } else {
        const size_t i = (size_t)(b - PB4) * 1024 + tid * 4;
        *(float4*)(Z + i) = make_float4(0.f, 0.f, 0.f, 0.f);
    }
}

// out = s0 + s1 + bias[col]  (fp32, 512 cols)
__global__ void add_splitk_bias(const float* __restrict__ s0, const float* __restrict__ s1,
                                const float* __restrict__ bias, float* __restrict__ out,
                                size_t n)
{
    size_t i = ((size_t)blockIdx.x * blockDim.x + threadIdx.x) * 4;
    const size_t stride = (size_t)gridDim.x * blockDim.x * 4;
    for (; i < n; i += stride) {
        float4 a = *(const float4*)(s0 + i);
        float4 b = *(const float4*)(s1 + i);
        const int c = (int)(i & 511);
        a.x += b.x + __ldg(&bias[c]);
        a.y += b.y + __ldg(&bias[c + 1]);
        a.z += b.z + __ldg(&bias[c + 2]);
        a.w += b.w + __ldg(&bias[c + 3]);
        *(float4*)(out + i) = a;
    }
}

// V^T per (b,h): Vt[d][sk] = h2h[(b,sk)][h*1536+1024+d]  (fp16)
__global__ void transpose_v(const __half* __restrict__ h2h,
                            __half* __restrict__ vth)
{
    __shared__ __half t[32][34];
    const int z = blockIdx.z, b = z >> 3, h = z & 7;
    const int sk0 = blockIdx.x * 32, d0 = blockIdx.y * 32;
    const int tx = threadIdx.x, ty = threadIdx.y;  // 32 x 8
    const size_t srcbase = (size_t)b * 2048 * 12288 + h * 1536 + 1024;
#pragma unroll
    for (int j = 0; j < 4; j++) {
        int sk = sk0 + ty + j * 8;
        t[ty + j * 8][tx] = h2h[srcbase + (size_t)sk * 12288 + d0 + tx];
    }
    __syncthreads();
    const size_t dstbase = (size_t)(b * 8 + h) * 512 * 2048;
#pragma unroll
    for (int j = 0; j < 4; j++) {
        int d = d0 + ty + j * 8;
        vth[dstbase + (size_t)d * 2048 + sk0 + tx] = t[tx][ty + j * 8];
    }
}

// =============================================================================
extern "C" void kernel_launch(void* const* d_in, const int* in_sizes, int n_in,
                              void* d_out, int out_size)
{
    const float* x     = (const float*)d_in[0];
    const float* W_sep = (const float*)d_in[1];
    const float* b_sep = (const float*)d_in[2];
    const float* W_mul = (const float*)d_in[3];
    const float* b_mul = (const float*)d_in[4];
    const float* W_res = (const float*)d_in[5];
    const float* b_res = (const float*)d_in[6];
    float* out = (float*)d_out;

    __half *xh, *Wmh, *Wst, *Wch, *Wrh, *h2h, *Ph, *Vth, *aph;
    float *beff, *sk, *Z;
    cudaGetSymbolAddress((void**)&xh,   g_xh);
    cudaGetSymbolAddress((void**)&Wmh,  g_Wmh);
    cudaGetSymbolAddress((void**)&Wst,  g_Wst);
    cudaGetSymbolAddress((void**)&Wch,  g_Wch);
    cudaGetSymbolAddress((void**)&beff, g_beff);
    cudaGetSymbolAddress((void**)&Wrh,  g_Wrh);
    cudaGetSymbolAddress((void**)&h2h,  g_h2h);
    cudaGetSymbolAddress((void**)&Z,    g_Z);
    cudaGetSymbolAddress((void**)&sk,   g_sk);
    cudaGetSymbolAddress((void**)&Ph,   g_Ph);
    cudaGetSymbolAddress((void**)&Vth,  g_Vth);
    cudaGetSymbolAddress((void**)&aph,  g_aph);

    cudaFuncSetAttribute(gemm_fp16<0>, cudaFuncAttributeMaxDynamicSharedMemorySize, SMEM_H);
    cudaFuncSetAttribute(gemm_fp16<1>, cudaFuncAttributeMaxDynamicSharedMemorySize, SMEM_H);
    cudaFuncSetAttribute(gemm_fp16<2>, cudaFuncAttributeMaxDynamicSharedMemorySize, SMEM_H);

    const size_t S = 2048, D = 512, H = 8;

    // (1) mega-prep: all conversions + W_sep^T + b_eff + zero Z
    prep_all<<<PB5, 256>>>(x, xh, W_mul, Wmh, W_res, Wrh, W_sep, Wst,
                           b_sep, b_mul, beff, Z);

    // (2) Wc = W_mul @ W_sep -> fp16 [12288, 512]
    gemm_fp16<0><<<dim3(4, 96, 1), 128, SMEM_H>>>(
        Wmh, Wst, nullptr, Wch, nullptr,
        1536, 1536, 1536, 512, 1, 0, 0, 0, 0, 0, 0, 0.f, nullptr);

    // (3) GEMM2': h2 = x @ Wc^T + b_eff  [4096 x 12288], K=512
    gemm_fp16<0><<<dim3(96, 32, 1), 128, SMEM_H>>>(
        xh, Wch, nullptr, h2h, beff,
        512, 512, 512, 12288, 1, 0, 0, 0, 0, 0, 0, 0.f, nullptr);

    // (4) QK^T fused softmax-producer (PROFILED): Ph = exp(scale*QK^T), Z += rowsums
    gemm_fp16<1><<<dim3(16, 16, 16), 128, SMEM_H>>>(
        h2h, h2h + 512, nullptr, Ph, nullptr,
        512, 12288, 12288, 2048, 8,
        1536, S * 12288, 1536, S * 12288,
        S * S, H * S * S, 1.0f / sqrtf(512.0f), Z);

    // (5) V^T (fp16)
    transpose_v<<<dim3(64, 16, 16), dim3(32, 8)>>>(h2h, Vth);

    // (6) PV normalizer-consumer: ap = (Ph @ Vt^T) / Z  [2048 x 512], K=2048
    gemm_fp16<2><<<dim3(4, 16, 16), 128, SMEM_H>>>(
        Ph, Vth, nullptr, aph, nullptr,
        2048, 2048, 2048, 4096, 8,
        S * S, H * S * S, D * S, H * D * S,
        512, S * 4096, 0.f, Z);

    // (7) GEMM3 split-K=2: fp32 partials into sk slabs
    gemm_fp16<0><<<dim3(4, 32, 2), 128, SMEM_H>>>(
        aph, Wrh, sk, nullptr, nullptr,
        2048, 4096, 4096, 512, 2,
        2048, 0, 2048, 0,
        4096UL * 512, 0, 0.f, nullptr);

    // (8) out = slab0 + slab1 + b_res
    add_splitk_bias<<<1024, 256>>>(sk, sk + 4096UL * 512, b_res, out, 4096UL * 512);
}

// round 17
// speedup vs baseline: 2.5437x; 1.0425x over previous
#include <cuda_runtime.h>
#include <cuda_fp16.h>
#include <math.h>
#include <stdint.h>

// ===================== scratch (static device arrays) ========================
__device__ __half g_xh [4096UL * 512];
__device__ __half g_Wmh[12288UL * 1536];
__device__ __half g_Wst[512UL * 1536];        // W_sep^T fp16
__device__ __half g_Wch[12288UL * 512];       // Wc = W_mul @ W_sep (fp16)
__device__ float  g_beff[12288];              // b_mul + W_mul @ b_sep (fp32)
__device__ __half g_Wrh[512UL * 4096];
__device__ __half g_h2h[4096UL * 12288];
__device__ float  g_Z  [16UL * 2048];         // softmax row sums
__device__ float  g_sk [4UL * 4096 * 512];    // split-K slabs fp32
__device__ __half g_Ph [16UL * 2048 * 2048];  // unnormalized exp scores fp16
__device__ __half g_aph[4096UL * 4096];

// ===================== helpers (base-target PTX only) ========================
__device__ __forceinline__ uint32_t smem_u32(const void* p) {
    uint32_t a;
    asm("{ .reg .u64 t; cvta.to.shared.u64 t, %1; cvt.u32.u64 %0, t; }"
        : "=r"(a) : "l"(p));
    return a;
}

__device__ __forceinline__ void cp16(uint32_t s, const void* g) {
    asm volatile("cp.async.cg.shared.global [%0], [%1], 16;"
                 :: "r"(s), "l"(g) : "memory");
}

__device__ __forceinline__ void ldsm4(uint32_t* r, uint32_t addr) {
    asm volatile("ldmatrix.sync.aligned.m8n8.x4.shared.b16 {%0,%1,%2,%3}, [%4];"
                 : "=r"(r[0]), "=r"(r[1]), "=r"(r[2]), "=r"(r[3]) : "r"(addr));
}

__device__ __forceinline__ void ldsm4t(uint32_t* r, uint32_t addr) {
    asm volatile("ldmatrix.sync.aligned.m8n8.x4.trans.shared.b16 {%0,%1,%2,%3}, [%4];"
                 : "=r"(r[0]), "=r"(r[1]), "=r"(r[2]), "=r"(r[3]) : "r"(addr));
}

__device__ __forceinline__ void mma_f16(float* c, const uint32_t* a, const uint32_t* b) {
    asm volatile(
        "mma.sync.aligned.m16n8k16.row.col.f32.f16.f16.f32 "
        "{%0,%1,%2,%3}, {%4,%5,%6,%7}, {%8,%9}, {%0,%1,%2,%3};"
        : "+f"(c[0]), "+f"(c[1]), "+f"(c[2]), "+f"(c[3])
        : "r"(a[0]), "r"(a[1]), "r"(a[2]), "r"(a[3]), "r"(b[0]), "r"(b[1]));
}

// 128B-row tile swizzle (128 rows x 64 fp16): 8 chunks of 16B
__device__ __forceinline__ uint32_t swzA(int row, int c) {
    return (uint32_t)(row * 128 + ((c ^ (row & 7)) << 4));
}
// 256B-row tile swizzle (64 k-rows x 128 fp16): 16 chunks of 16B
__device__ __forceinline__ uint32_t swzB(int row, int c) {
    return (uint32_t)(row * 256 + ((c ^ (row & 7)) << 4));
}

// ===================== fp16 GEMM (128x128x64, 64x64 warp tiles) ==============
// TRANSB=1: C = A @ B^T (B is N x K). TRANSB=0: C = A @ B (B is K x N).
// 128 thr (4 warps 2x2), K-chunk 64, 3-stage cp.async, 2 CTAs/SM.
// EPI: 0 = bias + write Cf/Ch; 1 = exp+rowsum producer; 2 = 1/Z normalizer.
#define ATK 16384                   // 128 x 64 fp16 (or 64 x 128)
#define STG (2 * ATK)               // 32768
#define NST 3
#define SMEMG (NST * STG)           // 98304

template <int EPI, bool TRANSB>
__global__ __launch_bounds__(128, 2)
void gemm_fp16(const __half* __restrict__ A, const __half* __restrict__ B,
               float* __restrict__ Cf, __half* __restrict__ Ch,
               const float* __restrict__ bias,
               int K, int lda, int ldb, int ldc, int NH,
               size_t sAh_, size_t sAb_, size_t sBh_, size_t sBb_,
               size_t sCh_, size_t sCb_, float scale, float* __restrict__ Z)
{
    extern __shared__ char smem[];
    const uint32_t sbase = smem_u32(smem);
    const int tid = threadIdx.x, lane = tid & 31, w = tid >> 5;
    const int wm = w & 1, wn = w >> 1;

    const int z = blockIdx.z, hb = z % NH, bb = z / NH;
    const size_t offA = (size_t)hb * sAh_ + (size_t)bb * sAb_;
    const size_t offB = (size_t)hb * sBh_ + (size_t)bb * sBb_;
    const size_t offC = (size_t)hb * sCh_ + (size_t)bb * sCb_;
    const int n0 = blockIdx.x * 128;

    const __half* ag = A + offA + (size_t)(blockIdx.y * 128) * lda;
    const __half* bg = TRANSB ? (B + offB + (size_t)n0 * ldb)
                              : (B + offB + n0);

    float acc[4][8][4];
#pragma unroll
    for (int mt = 0; mt < 4; mt++)
#pragma unroll
        for (int j = 0; j < 8; j++)
#pragma unroll
            for (int q = 0; q < 4; q++) acc[mt][j][q] = 0.0f;

    const int niter = K >> 6;

    auto issue = [&](int it) {
        const uint32_t sb = sbase + (uint32_t)(it % NST) * STG;
        const int k0 = it << 6;
        // A: 128 rows x 8 chunks = 1024 chunks -> 8/thread
#pragma unroll
        for (int q = 0; q < 8; q++) {
            const int idx = tid + q * 128;
            const int r = idx >> 3, c = idx & 7;
            cp16(sb + swzA(r, c), ag + (size_t)r * lda + k0 + c * 8);
        }
        if (TRANSB) {
#pragma unroll
            for (int q = 0; q < 8; q++) {
                const int idx = tid + q * 128;
                const int r = idx >> 3, c = idx & 7;
                cp16(sb + ATK + swzA(r, c), bg + (size_t)r * ldb + k0 + c * 8);
            }
        } else {
            // B: 64 k-rows x 16 chunks = 1024 chunks -> 8/thread
#pragma unroll
            for (int q = 0; q < 8; q++) {
                const int idx = tid + q * 128;
                const int r = idx >> 4, c = idx & 15;
                cp16(sb + ATK + swzB(r, c), bg + (size_t)(k0 + r) * ldb + c * 8);
            }
        }
        asm volatile("cp.async.commit_group;" ::: "memory");
    };

    issue(0);
    if (niter > 1) issue(1);

    for (int i = 0; i < niter; i++) {
        if (i + 1 < niter)
            asm volatile("cp.async.wait_group 1;" ::: "memory");
        else
            asm volatile("cp.async.wait_group 0;" ::: "memory");
        __syncthreads();
        if (i + 2 < niter) issue(i + 2);

        const uint32_t sb = sbase + (uint32_t)(i % NST) * STG;
        const uint32_t sbB = sb + ATK;
#pragma unroll
        for (int k16 = 0; k16 < 4; k16++) {
            uint32_t af[4][4], bf[4][4];
            {
                const int rA = wm * 64 + (lane & 15);
                const int cA = k16 * 2 + (lane >> 4);
#pragma unroll
                for (int mt = 0; mt < 4; mt++)
                    ldsm4(af[mt], sb + swzA(rA + mt * 16, cA));
            }
            if (TRANSB) {
                const int rB = wn * 64 + (lane & 7) + ((lane >> 4) << 3);
                const int cB = k16 * 2 + ((lane >> 3) & 1);
#pragma unroll
                for (int nt = 0; nt < 4; nt++)
                    ldsm4(bf[nt], sbB + swzA(rB + nt * 16, cB));
            } else {
                const int kk = k16 * 16 + (lane & 15);
#pragma unroll
                for (int nt = 0; nt < 4; nt++) {
                    const int c = wn * 8 + nt * 2 + (lane >> 4);
                    ldsm4t(bf[nt], sbB + swzB(kk, c));
                }
            }
#pragma unroll
            for (int mt = 0; mt < 4; mt++)
#pragma unroll
                for (int nt = 0; nt < 4; nt++) {
                    mma_f16(acc[mt][nt * 2],     af[mt], &bf[nt][0]);
                    mma_f16(acc[mt][nt * 2 + 1], af[mt], &bf[nt][2]);
                }
        }
    }

    // ---------------- epilogue ----------------
    const int gid = lane >> 2, tig = lane & 3;
    const int row0 = blockIdx.y * 128 + wm * 64;
    const int col0 = n0 + wn * 64;
#pragma unroll
    for (int mt = 0; mt < 4; mt++) {
        const int r = row0 + mt * 16 + gid;
        float sum_r = 0.0f, sum_r8 = 0.0f;
        float iz0 = 1.0f, iz1 = 1.0f;
        if (EPI == 2) {
            iz0 = 1.0f / __ldg(&Z[(size_t)z * 2048 + r]);
            iz1 = 1.0f / __ldg(&Z[(size_t)z * 2048 + r + 8]);
        }
#pragma unroll
        for (int j = 0; j < 8; j++) {
            const int c = col0 + j * 8 + tig * 2;
            float v0 = acc[mt][j][0], v1 = acc[mt][j][1];
            float v2 = acc[mt][j][2], v3 = acc[mt][j][3];
            const size_t o0 = offC + (size_t)r * ldc + c;
            const size_t o1 = offC + (size_t)(r + 8) * ldc + c;
            if (EPI == 0) {
                float b0 = 0.f, b1 = 0.f;
                if (bias) { b0 = __ldg(&bias[c]); b1 = __ldg(&bias[c + 1]); }
                v0 += b0; v1 += b1; v2 += b0; v3 += b1;
                if (Ch) {
                    *(__half2*)(Ch + o0) = __floats2half2_rn(v0, v1);
                    *(__half2*)(Ch + o1) = __floats2half2_rn(v2, v3);
                }
                if (Cf) {
                    *(float2*)(Cf + o0) = make_float2(v0, v1);
                    *(float2*)(Cf + o1) = make_float2(v2, v3);
                }
            } else if (EPI == 1) {
                v0 = __expf(fminf(v0 * scale, 11.0f));
                v1 = __expf(fminf(v1 * scale, 11.0f));
                v2 = __expf(fminf(v2 * scale, 11.0f));
                v3 = __expf(fminf(v3 * scale, 11.0f));
                sum_r  += v0 + v1;
                sum_r8 += v2 + v3;
                *(__half2*)(Ch + o0) = __floats2half2_rn(v0, v1);
                *(__half2*)(Ch + o1) = __floats2half2_rn(v2, v3);
            } else {
                *(__half2*)(Ch + o0) = __floats2half2_rn(v0 * iz0, v1 * iz0);
                *(__half2*)(Ch + o1) = __floats2half2_rn(v2 * iz1, v3 * iz1);
            }
        }
        if (EPI == 1) {
            sum_r  += __shfl_xor_sync(0xFFFFFFFF, sum_r, 1);
            sum_r  += __shfl_xor_sync(0xFFFFFFFF, sum_r, 2);
            sum_r8 += __shfl_xor_sync(0xFFFFFFFF, sum_r8, 1);
            sum_r8 += __shfl_xor_sync(0xFFFFFFFF, sum_r8, 2);
            if (tig == 0) {
                atomicAdd(&Z[(size_t)z * 2048 + r],     sum_r);
                atomicAdd(&Z[(size_t)z * 2048 + r + 8], sum_r8);
            }
        }
    }
}

// ===================== mega-prep kernel ======================================
#define PB0 2048
#define PB1 20480
#define PB2 22528
#define PB3 23296
#define PB4 23392
#define PB5 23424

__global__ void prep_all(const float* __restrict__ x,     __half* __restrict__ xh,
                         const float* __restrict__ Wmul,  __half* __restrict__ Wmh,
                         const float* __restrict__ Wres,  __half* __restrict__ Wrh,
                         const float* __restrict__ Wsep,  __half* __restrict__ Wst,
                         const float* __restrict__ bsep,  const float* __restrict__ bmul,
                         float* __restrict__ beff, float* __restrict__ Z)
{
    const int b = blockIdx.x, tid = threadIdx.x;
    if (b < PB2) {
        const float* in;
        __half* out;
        size_t base;
        if (b < PB0)      { in = x;    out = xh;  base = (size_t)b * 1024; }
        else if (b < PB1) { in = Wmul; out = Wmh; base = (size_t)(b - PB0) * 1024; }
        else              { in = Wres; out = Wrh; base = (size_t)(b - PB1) * 1024; }
        const size_t i = base + (size_t)tid * 4;
        float4 v = *(const float4*)(in + i);
        *(__half2*)(out + i)     = __floats2half2_rn(v.x, v.y);
        *(__half2*)(out + i + 2) = __floats2half2_rn(v.z, v.w);
    } else if (b < PB3) {
        __shared__ float t[32][33];
        const int bb = b - PB2;
        const int tx = tid & 31, ty = tid >> 5;
        const int e0 = (bb % 48) * 32;
        const int d0 = (bb / 48) * 32;
#pragma unroll
        for (int j = 0; j < 4; j++)
            t[ty + j * 8][tx] = Wsep[(size_t)(e0 + ty + j * 8) * 512 + d0 + tx];
        __syncthreads();
#pragma unroll
        for (int j = 0; j < 4; j++)
            Wst[(size_t)(d0 + ty + j * 8) * 1536 + e0 + tx] =
                __float2half(t[tx][ty + j * 8]);
    } else if (b < PB4) {
        const int lane = tid & 31, wrp = tid >> 5;
        const int wglobal = (b - PB3) * 8 + wrp;
#pragma unroll 1
        for (int t = 0; t < 16; t++) {
            const int f = wglobal * 16 + t;
            const float* row = Wmul + (size_t)f * 1536;
            float s = 0.0f;
            for (int e = lane; e < 1536; e += 32)
                s = fmaf(row[e], __ldg(&bsep[e]), s);
#pragma unroll
            for (int o = 16; o > 0; o >>= 1)
                s += __shfl_down_sync(0xFFFFFFFF, s, o);
            if (lane == 0) beff[f] = s + bmul[f];
        }
    } else {
        const size_t i = (size_t)(b - PB4) * 1024 + tid * 4;
        *(float4*)(Z + i) = make_float4(0.f, 0.f, 0.f, 0.f);
    }
}

// out = s0+s1+s2+s3 + bias[col]  (fp32, 512 cols)
__global__ void add_splitk_bias(const float* __restrict__ sk,
                                const float* __restrict__ bias,
                                float* __restrict__ out, size_t n)
{
    size_t i = ((size_t)blockIdx.x * blockDim.x + threadIdx.x) * 4;
    const size_t stride = (size_t)gridDim.x * blockDim.x * 4;
    for (; i < n; i += stride) {
        float4 a = *(const float4*)(sk + i);
        float4 b = *(const float4*)(sk + n + i);
        float4 c = *(const float4*)(sk + 2 * n + i);
        float4 d = *(const float4*)(sk + 3 * n + i);
        const int col = (int)(i & 511);
        a.x += b.x + c.x + d.x + __ldg(&bias[col]);
        a.y += b.y + c.y + d.y + __ldg(&bias[col + 1]);
        a.z += b.z + c.z + d.z + __ldg(&bias[col + 2]);
        a.w += b.w + c.w + d.w + __ldg(&bias[col + 3]);
        *(float4*)(out + i) = a;
    }
}

// =============================================================================
extern "C" void kernel_launch(void* const* d_in, const int* in_sizes, int n_in,
                              void* d_out, int out_size)
{
    const float* x     = (const float*)d_in[0];
    const float* W_sep = (const float*)d_in[1];
    const float* b_sep = (const float*)d_in[2];
    const float* W_mul = (const float*)d_in[3];
    const float* b_mul = (const float*)d_in[4];
    const float* W_res = (const float*)d_in[5];
    const float* b_res = (const float*)d_in[6];
    float* out = (float*)d_out;

    __half *xh, *Wmh, *Wst, *Wch, *Wrh, *h2h, *Ph, *aph;
    float *beff, *sk, *Z;
    cudaGetSymbolAddress((void**)&xh,   g_xh);
    cudaGetSymbolAddress((void**)&Wmh,  g_Wmh);
    cudaGetSymbolAddress((void**)&Wst,  g_Wst);
    cudaGetSymbolAddress((void**)&Wch,  g_Wch);
    cudaGetSymbolAddress((void**)&beff, g_beff);
    cudaGetSymbolAddress((void**)&Wrh,  g_Wrh);
    cudaGetSymbolAddress((void**)&h2h,  g_h2h);
    cudaGetSymbolAddress((void**)&Z,    g_Z);
    cudaGetSymbolAddress((void**)&sk,   g_sk);
    cudaGetSymbolAddress((void**)&Ph,   g_Ph);
    cudaGetSymbolAddress((void**)&aph,  g_aph);

    cudaFuncSetAttribute((const void*)gemm_fp16<0, true>,  cudaFuncAttributeMaxDynamicSharedMemorySize, SMEMG);
    cudaFuncSetAttribute((const void*)gemm_fp16<1, true>,  cudaFuncAttributeMaxDynamicSharedMemorySize, SMEMG);
    cudaFuncSetAttribute((const void*)gemm_fp16<2, false>, cudaFuncAttributeMaxDynamicSharedMemorySize, SMEMG);

    const size_t S = 2048, D = 512, H = 8;

    // (1) mega-prep
    prep_all<<<PB5, 256>>>(x, xh, W_mul, Wmh, W_res, Wrh, W_sep, Wst,
                           b_sep, b_mul, beff, Z);

    // (2) Wc = W_mul @ W_sep^T' -> fp16 [12288, 512], K=1536
    gemm_fp16<0, true><<<dim3(4, 96, 1), 128, SMEMG>>>(
        Wmh, Wst, nullptr, Wch, nullptr,
        1536, 1536, 1536, 512, 1, 0, 0, 0, 0, 0, 0, 0.f, nullptr);

    // (3) GEMM2': h2 = x @ Wc^T + b_eff  [4096 x 12288], K=512
    gemm_fp16<0, true><<<dim3(96, 32, 1), 128, SMEMG>>>(
        xh, Wch, nullptr, h2h, beff,
        512, 512, 512, 12288, 1, 0, 0, 0, 0, 0, 0, 0.f, nullptr);

    // (4) QK^T fused softmax-producer (PROFILED)
    gemm_fp16<1, true><<<dim3(16, 16, 16), 128, SMEMG>>>(
        h2h, h2h + 512, nullptr, Ph, nullptr,
        512, 12288, 12288, 2048, 8,
        1536, S * 12288, 1536, S * 12288,
        S * S, H * S * S, 1.0f / sqrtf(512.0f), Z);

    // (5) PV (NN mode, B = V in K-major straight from h2) + normalizer
    gemm_fp16<2, false><<<dim3(4, 16, 16), 128, SMEMG>>>(
        Ph, h2h + 1024, nullptr, aph, nullptr,
        2048, 2048, 12288, 4096, 8,
        S * S, H * S * S, 1536, S * 12288,
        512, S * 4096, 0.f, Z);

    // (6) GEMM3 split-K=4: fp32 partials into 4 sk slabs
    gemm_fp16<0, true><<<dim3(4, 32, 4), 128, SMEMG>>>(
        aph, Wrh, sk, nullptr, nullptr,
        1024, 4096, 4096, 512, 4,
        1024, 0, 1024, 0,
        4096UL * 512, 0, 0.f, nullptr);

    // (7) out = sum of 4 slabs + b_res
    add_splitk_bias<<<1024, 256>>>(sk, b_res, out, 4096UL * 512);
}